// round 2
// baseline (speedup 1.0000x reference)
#include <cuda_runtime.h>
#include <math.h>

// Problem constants
#define BB 32
#define SS 744
#define DD 512
#define HH 8
#define HD 64
#define LL 4
#define MM (BB*SS)     // 23808 = 64*372
#define FF (4*DD)      // 2048

// ---------------------------------------------------------------------------
// Scratch (device globals; no runtime allocation allowed)
// ---------------------------------------------------------------------------
__device__ float g_h [MM*DD];
__device__ float g_q [MM*DD];
__device__ float g_k [MM*DD];
__device__ float g_v [MM*DD];
__device__ float g_o [MM*DD];
__device__ float g_t [MM*DD];
__device__ float g_n1[MM*DD];
__device__ float g_ff[(size_t)MM*FF];

// ---------------------------------------------------------------------------
// Embedding: h[b,s,d] = emb[x[b,s],d]*sqrt(D) + pe[s,d]
// ---------------------------------------------------------------------------
__global__ void embed_kernel(const int* __restrict__ x,
                             const float* __restrict__ emb,
                             const float* __restrict__ pe,
                             float* __restrict__ h)
{
    int idx = blockIdx.x * 256 + threadIdx.x;       // < MM*DD
    int d   = idx & (DD - 1);
    int ms  = idx >> 9;                              // b*S + s
    int s   = ms % SS;
    int tok = x[ms];
    h[idx] = emb[tok * DD + d] * 22.627416997969522f + pe[s * DD + d];
}

// ---------------------------------------------------------------------------
// QKV projection: q[b,h,s,e] = sum_d h[b,s,h*64+d] * Wq[e,d]   (per head)
// grid = (B*H, S/4), block = 256 (4 s-rows x 64 e)
// ---------------------------------------------------------------------------
__global__ void qkv_kernel(const float* __restrict__ h,
                           const float* __restrict__ Wq,
                           const float* __restrict__ Wk,
                           const float* __restrict__ Wv,
                           float* __restrict__ q,
                           float* __restrict__ k,
                           float* __restrict__ v)
{
    int bh = blockIdx.x;
    int b  = bh >> 3;
    int hh = bh & 7;
    int sl = threadIdx.x >> 6;
    int e  = threadIdx.x & 63;
    int s  = blockIdx.y * 4 + sl;

    __shared__ float xs[4][64];
    xs[sl][e] = h[((size_t)(b * SS + s)) * DD + hh * HD + e];
    __syncthreads();

    const float* wq = Wq + e * HD;
    const float* wk = Wk + e * HD;
    const float* wv = Wv + e * HD;

    float aq = 0.f, ak = 0.f, av = 0.f;
#pragma unroll
    for (int d = 0; d < HD; d++) {
        float xv = xs[sl][d];
        aq += xv * __ldg(wq + d);
        ak += xv * __ldg(wk + d);
        av += xv * __ldg(wv + d);
    }
    size_t oi = ((size_t)bh * SS + s) * HD + e;
    q[oi] = aq; k[oi] = ak; v[oi] = av;
}

// ---------------------------------------------------------------------------
// Attention: warp-per-query online softmax.
// Q,K,V: [B,H,S,64]; O written in [B,S,D] layout (d = h*64+e).
// grid = (B*H, S/8), block = 256 (8 warps)
// ---------------------------------------------------------------------------
__global__ void attn_kernel(const float* __restrict__ Q,
                            const float* __restrict__ K,
                            const float* __restrict__ V,
                            float* __restrict__ O)
{
    int bh   = blockIdx.x;
    int w    = threadIdx.x >> 5;
    int lane = threadIdx.x & 31;
    int s    = blockIdx.y * 8 + w;

    const float* qp = Q + ((size_t)bh * SS + s) * HD;
    float q0 = qp[lane];
    float q1 = qp[lane + 32];

    const float* Kb = K + (size_t)bh * SS * HD;
    const float* Vb = V + (size_t)bh * SS * HD;

    float m = -INFINITY, l = 0.f, a0 = 0.f, a1 = 0.f;

    for (int t = 0; t < SS; t++) {
        const float* kt = Kb + t * HD;
        float x = q0 * kt[lane] + q1 * kt[lane + 32];
#pragma unroll
        for (int off = 16; off; off >>= 1)
            x += __shfl_xor_sync(0xffffffffu, x, off);
        x *= 0.125f;                         // 1/sqrt(64)

        float mn = fmaxf(m, x);
        float c  = __expf(m - mn);           // 0 on first iter (m=-inf)
        float p  = __expf(x - mn);
        l  = l * c + p;
        const float* vt = Vb + t * HD;
        a0 = a0 * c + p * vt[lane];
        a1 = a1 * c + p * vt[lane + 32];
        m  = mn;
    }

    int b  = bh >> 3;
    int hh = bh & 7;
    float inv = 1.f / l;
    float* op = O + ((size_t)(b * SS + s)) * DD + hh * HD;
    op[lane]      = a0 * inv;
    op[lane + 32] = a1 * inv;
}

// ---------------------------------------------------------------------------
// Tiled SGEMM: C[m,n] = sum_k A[m,k]*W[n,k] (+bias[n]) (ReLU) (+R[m,n])
// BM=BN=64, BK=16, 256 threads, 4x4 microtile. M%64==0, N%64==0, K%16==0.
// ---------------------------------------------------------------------------
template<bool RELU, bool RESID>
__global__ void gemm_kernel(const float* __restrict__ A,
                            const float* __restrict__ W,
                            const float* __restrict__ bias,
                            const float* __restrict__ R,
                            float* __restrict__ C,
                            int M, int N, int K)
{
    __shared__ float As[16][68];
    __shared__ float Ws[16][68];

    int tid = threadIdx.x;
    int tx  = tid & 15;
    int ty  = tid >> 4;
    int m0  = blockIdx.y * 64;
    int n0  = blockIdx.x * 64;

    int lr = tid >> 2;            // 0..63 (row within tile)
    int lk = (tid & 3) * 4;       // 0,4,8,12

    const float* Ap = A + (size_t)(m0 + lr) * K + lk;
    const float* Wp = W + (size_t)(n0 + lr) * K + lk;

    float acc[4][4] = {};

    for (int k0 = 0; k0 < K; k0 += 16) {
        float4 av = *(const float4*)(Ap + k0);
        float4 wv = *(const float4*)(Wp + k0);
        As[lk + 0][lr] = av.x; As[lk + 1][lr] = av.y;
        As[lk + 2][lr] = av.z; As[lk + 3][lr] = av.w;
        Ws[lk + 0][lr] = wv.x; Ws[lk + 1][lr] = wv.y;
        Ws[lk + 2][lr] = wv.z; Ws[lk + 3][lr] = wv.w;
        __syncthreads();

#pragma unroll
        for (int kk = 0; kk < 16; kk++) {
            float a[4], bv[4];
#pragma unroll
            for (int i = 0; i < 4; i++) a[i]  = As[kk][ty * 4 + i];
#pragma unroll
            for (int j = 0; j < 4; j++) bv[j] = Ws[kk][tx * 4 + j];
#pragma unroll
            for (int i = 0; i < 4; i++)
#pragma unroll
                for (int j = 0; j < 4; j++)
                    acc[i][j] += a[i] * bv[j];
        }
        __syncthreads();
    }

#pragma unroll
    for (int i = 0; i < 4; i++) {
        int m = m0 + ty * 4 + i;
#pragma unroll
        for (int j = 0; j < 4; j++) {
            int n = n0 + tx * 4 + j;
            float vv = acc[i][j] + bias[n];
            if (RELU)  vv = fmaxf(vv, 0.f);
            if (RESID) vv += R[(size_t)m * N + n];
            C[(size_t)m * N + n] = vv;
        }
    }
}

// ---------------------------------------------------------------------------
// LayerNorm over last dim (512). One block per row, 256 threads.
// ---------------------------------------------------------------------------
__global__ void ln_kernel(const float* __restrict__ x,
                          const float* __restrict__ w,
                          const float* __restrict__ b,
                          float* __restrict__ y)
{
    int r = blockIdx.x;
    int t = threadIdx.x;
    const float* xr = x + (size_t)r * DD;

    float v0 = xr[t], v1 = xr[t + 256];
    float s  = v0 + v1;
    float sq = v0 * v0 + v1 * v1;

#pragma unroll
    for (int off = 16; off; off >>= 1) {
        s  += __shfl_xor_sync(0xffffffffu, s,  off);
        sq += __shfl_xor_sync(0xffffffffu, sq, off);
    }
    __shared__ float sw[8], sqw[8];
    if ((t & 31) == 0) { sw[t >> 5] = s; sqw[t >> 5] = sq; }
    __syncthreads();
    s  = sw[0] + sw[1] + sw[2] + sw[3] + sw[4] + sw[5] + sw[6] + sw[7];
    sq = sqw[0] + sqw[1] + sqw[2] + sqw[3] + sqw[4] + sqw[5] + sqw[6] + sqw[7];

    float mean = s * (1.f / DD);
    float var  = sq * (1.f / DD) - mean * mean;
    float inv  = rsqrtf(var + 1e-5f);

    float* yr = y + (size_t)r * DD;
    yr[t]       = (v0 - mean) * inv * w[t]       + b[t];
    yr[t + 256] = (v1 - mean) * inv * w[t + 256] + b[t + 256];
}

// ---------------------------------------------------------------------------
// Host launcher
// ---------------------------------------------------------------------------
extern "C" void kernel_launch(void* const* d_in, const int* in_sizes, int n_in,
                              void* d_out, int out_size)
{
    const int*   x    = (const int*)  d_in[0];
    const float* emb  = (const float*)d_in[1];
    const float* pe   = (const float*)d_in[2];
    const float* Wq   = (const float*)d_in[3];
    const float* Wk   = (const float*)d_in[4];
    const float* Wv   = (const float*)d_in[5];
    const float* Wo   = (const float*)d_in[6];
    const float* bo   = (const float*)d_in[7];
    const float* ln1w = (const float*)d_in[8];
    const float* ln1b = (const float*)d_in[9];
    const float* W1   = (const float*)d_in[10];
    const float* b1   = (const float*)d_in[11];
    const float* W2   = (const float*)d_in[12];
    const float* b2   = (const float*)d_in[13];
    const float* ln2w = (const float*)d_in[14];
    const float* ln2b = (const float*)d_in[15];
    float* out = (float*)d_out;

    float *h, *q, *k, *v, *o, *t, *n1, *ff;
    cudaGetSymbolAddress((void**)&h,  g_h);
    cudaGetSymbolAddress((void**)&q,  g_q);
    cudaGetSymbolAddress((void**)&k,  g_k);
    cudaGetSymbolAddress((void**)&v,  g_v);
    cudaGetSymbolAddress((void**)&o,  g_o);
    cudaGetSymbolAddress((void**)&t,  g_t);
    cudaGetSymbolAddress((void**)&n1, g_n1);
    cudaGetSymbolAddress((void**)&ff, g_ff);

    embed_kernel<<<MM * DD / 256, 256>>>(x, emb, pe, h);

    for (int l = 0; l < LL; l++) {
        qkv_kernel<<<dim3(BB * HH, SS / 4), 256>>>(
            h, Wq + l * HD * HD, Wk + l * HD * HD, Wv + l * HD * HD, q, k, v);

        attn_kernel<<<dim3(BB * HH, SS / 8), 256>>>(q, k, v, o);

        // t = o @ Wo^T + bo + h
        gemm_kernel<false, true><<<dim3(DD / 64, MM / 64), 256>>>(
            o, Wo + (size_t)l * DD * DD, bo + l * DD, h, t, MM, DD, DD);

        ln_kernel<<<MM, 256>>>(t, ln1w + l * DD, ln1b + l * DD, n1);

        // ff = relu(n1 @ W1^T + b1)
        gemm_kernel<true, false><<<dim3(FF / 64, MM / 64), 256>>>(
            n1, W1 + (size_t)l * FF * DD, b1 + l * FF, nullptr, ff, MM, FF, DD);

        // t = ff @ W2^T + b2 + n1
        gemm_kernel<false, true><<<dim3(DD / 64, MM / 64), 256>>>(
            ff, W2 + (size_t)l * DD * FF, b2 + l * DD, n1, t, MM, DD, FF);

        float* dst = (l == LL - 1) ? out : h;
        ln_kernel<<<MM, 256>>>(t, ln2w + l * DD, ln2b + l * DD, dst);
    }
}

// round 3
// speedup vs baseline: 1.3040x; 1.3040x over previous
#include <cuda_runtime.h>
#include <math.h>

// Problem constants
#define BB 32
#define SS 744
#define DD 512
#define HH 8
#define HD 64
#define LL 4
#define MM (BB*SS)     // 23808 = 64*372
#define FF (4*DD)      // 2048

#define QT 32          // queries per block (attention)
#define KT 32          // keys per tile (attention)
#define NQT ((SS + QT - 1) / QT)   // 24

// ---------------------------------------------------------------------------
// Scratch (device globals; no runtime allocation allowed)
// ---------------------------------------------------------------------------
__device__ float g_h [MM*DD];
__device__ float g_q [MM*DD];
__device__ float g_k [MM*DD];
__device__ float g_v [MM*DD];
__device__ float g_o [MM*DD];
__device__ float g_t [MM*DD];
__device__ float g_n1[MM*DD];
__device__ float g_ff[(size_t)MM*FF];

// ---------------------------------------------------------------------------
// Embedding: h[b,s,d] = emb[x[b,s],d]*sqrt(D) + pe[s,d]
// ---------------------------------------------------------------------------
__global__ void embed_kernel(const int* __restrict__ x,
                             const float* __restrict__ emb,
                             const float* __restrict__ pe,
                             float* __restrict__ h)
{
    int idx = blockIdx.x * 256 + threadIdx.x;       // < MM*DD
    int d   = idx & (DD - 1);
    int ms  = idx >> 9;                              // b*S + s
    int s   = ms % SS;
    int tok = x[ms];
    h[idx] = emb[tok * DD + d] * 22.627416997969522f + pe[s * DD + d];
}

// ---------------------------------------------------------------------------
// QKV projection: q[b,h,s,e] = sum_d h[b,s,h*64+d] * Wq[e,d]   (per head)
// grid = (B*H, S/4), block = 256 (4 s-rows x 64 e)
// ---------------------------------------------------------------------------
__global__ void qkv_kernel(const float* __restrict__ h,
                           const float* __restrict__ Wq,
                           const float* __restrict__ Wk,
                           const float* __restrict__ Wv,
                           float* __restrict__ q,
                           float* __restrict__ k,
                           float* __restrict__ v)
{
    int bh = blockIdx.x;
    int b  = bh >> 3;
    int hh = bh & 7;
    int sl = threadIdx.x >> 6;
    int e  = threadIdx.x & 63;
    int s  = blockIdx.y * 4 + sl;

    __shared__ float xs[4][64];
    xs[sl][e] = h[((size_t)(b * SS + s)) * DD + hh * HD + e];
    __syncthreads();

    const float* wq = Wq + e * HD;
    const float* wk = Wk + e * HD;
    const float* wv = Wv + e * HD;

    float aq = 0.f, ak = 0.f, av = 0.f;
#pragma unroll
    for (int d = 0; d < HD; d++) {
        float xv = xs[sl][d];
        aq += xv * __ldg(wq + d);
        ak += xv * __ldg(wk + d);
        av += xv * __ldg(wv + d);
    }
    size_t oi = ((size_t)bh * SS + s) * HD + e;
    q[oi] = aq; k[oi] = ak; v[oi] = av;
}

// ---------------------------------------------------------------------------
// Attention v2: smem-tiled flash attention.
// grid = (B*H, NQT); block = 256 (8 warps). Each block: 32 queries.
// Each warp owns 4 queries; keys processed in 32-wide tiles; lane j holds
// the score for key j  ->  1 exp / 10 shfl per (query, 32-key tile).
// ---------------------------------------------------------------------------
__global__ __launch_bounds__(256) void attn2_kernel(
        const float* __restrict__ Q,
        const float* __restrict__ K,
        const float* __restrict__ V,
        float* __restrict__ O)
{
    __shared__ float Ks[HD][KT + 1];   // transposed K tile [d][j]
    __shared__ float Vs[KT][HD];       // V tile [j][e]
    __shared__ float Qs[QT][HD];       // Q tile [q][d]
    __shared__ float Ps[8][4][KT];     // per-warp softmax weights

    const int bh   = blockIdx.x;
    const int qt   = blockIdx.y;
    const int tid  = threadIdx.x;
    const int w    = tid >> 5;
    const int lane = tid & 31;

    const float* Qb = Q + (size_t)bh * SS * HD;
    const float* Kb = K + (size_t)bh * SS * HD;
    const float* Vb = V + (size_t)bh * SS * HD;

    // ---- load Q tile (32 x 64 floats = 512 float4) ----
    {
        const float4* Q4 = (const float4*)Qb;
#pragma unroll
        for (int i = 0; i < 2; i++) {
            int f   = tid + i * 256;      // float4 index 0..511
            int row = f >> 4;             // query within tile
            int c4  = f & 15;
            int sg  = qt * QT + row;
            if (sg > SS - 1) sg = SS - 1; // clamp (unused rows)
            ((float4*)Qs)[row * 16 + c4] = Q4[(size_t)sg * 16 + c4];
        }
    }

    // per-warp query state (4 queries)
    float m[4], l[4], o0[4], o1[4];
#pragma unroll
    for (int q = 0; q < 4; q++) { m[q] = -INFINITY; l[q] = 0.f; o0[q] = 0.f; o1[q] = 0.f; }

    const int kj = tid >> 3;          // key row this thread copies (0..31)
    const int dg = (tid & 7) * 8;     // 8-float chunk within the 64-dim row

    for (int kt = 0; kt < NQT; kt++) {
        int t0 = kt * KT;
        int nk = SS - t0; if (nk > KT) nk = KT;

        __syncthreads();   // prior tile fully consumed before overwrite

        // ---- load K (transposed) and V tiles ----
        {
            int tr = t0 + kj; if (tr > SS - 1) tr = SS - 1;
            const float4* kr = (const float4*)(Kb + (size_t)tr * HD + dg);
            float4 k0 = kr[0], k1 = kr[1];
            Ks[dg + 0][kj] = k0.x; Ks[dg + 1][kj] = k0.y;
            Ks[dg + 2][kj] = k0.z; Ks[dg + 3][kj] = k0.w;
            Ks[dg + 4][kj] = k1.x; Ks[dg + 5][kj] = k1.y;
            Ks[dg + 6][kj] = k1.z; Ks[dg + 7][kj] = k1.w;
            const float4* vr = (const float4*)(Vb + (size_t)tr * HD + dg);
            ((float4*)&Vs[kj][dg])[0] = vr[0];
            ((float4*)&Vs[kj][dg])[1] = vr[1];
        }
        __syncthreads();

        // ---- scores: lane holds key j = lane; 4 queries per warp ----
        float s0 = 0.f, s1 = 0.f, s2 = 0.f, s3 = 0.f;
        const float4* q0p = (const float4*)Qs[w * 4 + 0];
        const float4* q1p = (const float4*)Qs[w * 4 + 1];
        const float4* q2p = (const float4*)Qs[w * 4 + 2];
        const float4* q3p = (const float4*)Qs[w * 4 + 3];
#pragma unroll
        for (int d4 = 0; d4 < 16; d4++) {
            float k0 = Ks[d4 * 4 + 0][lane];
            float k1 = Ks[d4 * 4 + 1][lane];
            float k2 = Ks[d4 * 4 + 2][lane];
            float k3 = Ks[d4 * 4 + 3][lane];
            float4 a;
            a = q0p[d4]; s0 += a.x*k0 + a.y*k1 + a.z*k2 + a.w*k3;
            a = q1p[d4]; s1 += a.x*k0 + a.y*k1 + a.z*k2 + a.w*k3;
            a = q2p[d4]; s2 += a.x*k0 + a.y*k1 + a.z*k2 + a.w*k3;
            a = q3p[d4]; s3 += a.x*k0 + a.y*k1 + a.z*k2 + a.w*k3;
        }
        float sc[4] = { s0 * 0.125f, s1 * 0.125f, s2 * 0.125f, s3 * 0.125f };
        if (lane >= nk) { sc[0] = sc[1] = sc[2] = sc[3] = -1e30f; }

        // ---- online softmax update (lane-parallel over keys) ----
#pragma unroll
        for (int q = 0; q < 4; q++) {
            float tmax = sc[q];
#pragma unroll
            for (int off = 16; off; off >>= 1)
                tmax = fmaxf(tmax, __shfl_xor_sync(0xffffffffu, tmax, off));
            float nm = fmaxf(m[q], tmax);
            float c  = __expf(m[q] - nm);     // 0 on first tile
            float p  = __expf(sc[q] - nm);
            float ps = p;
#pragma unroll
            for (int off = 16; off; off >>= 1)
                ps += __shfl_xor_sync(0xffffffffu, ps, off);
            l[q]  = l[q] * c + ps;
            o0[q] *= c;  o1[q] *= c;
            m[q]  = nm;
            Ps[w][q][lane] = p;
        }
        __syncwarp();

        // ---- accumulate O: o[e] += sum_j p_j * V[j][e] ----
#pragma unroll
        for (int j = 0; j < KT; j++) {
            float v0 = Vs[j][lane];
            float v1 = Vs[j][lane + 32];
            float p0 = Ps[w][0][j], p1 = Ps[w][1][j];
            float p2 = Ps[w][2][j], p3 = Ps[w][3][j];
            o0[0] += p0 * v0;  o1[0] += p0 * v1;
            o0[1] += p1 * v0;  o1[1] += p1 * v1;
            o0[2] += p2 * v0;  o1[2] += p2 * v1;
            o0[3] += p3 * v0;  o1[3] += p3 * v1;
        }
    }

    // ---- epilogue: write O in [B,S,D] layout (d = h*64+e) ----
    int b  = bh >> 3;
    int hh = bh & 7;
#pragma unroll
    for (int q = 0; q < 4; q++) {
        int s = qt * QT + w * 4 + q;
        if (s < SS) {
            float inv = 1.f / l[q];
            float* op = O + ((size_t)(b * SS + s)) * DD + hh * HD;
            op[lane]      = o0[q] * inv;
            op[lane + 32] = o1[q] * inv;
        }
    }
}

// ---------------------------------------------------------------------------
// Tiled SGEMM: C[m,n] = sum_k A[m,k]*W[n,k] (+bias[n]) (ReLU) (+R[m,n])
// BM=BN=64, BK=16, 256 threads, 4x4 microtile. M%64==0, N%64==0, K%16==0.
// ---------------------------------------------------------------------------
template<bool RELU, bool RESID>
__global__ void gemm_kernel(const float* __restrict__ A,
                            const float* __restrict__ W,
                            const float* __restrict__ bias,
                            const float* __restrict__ R,
                            float* __restrict__ C,
                            int M, int N, int K)
{
    __shared__ float As[16][68];
    __shared__ float Ws[16][68];

    int tid = threadIdx.x;
    int tx  = tid & 15;
    int ty  = tid >> 4;
    int m0  = blockIdx.y * 64;
    int n0  = blockIdx.x * 64;

    int lr = tid >> 2;            // 0..63 (row within tile)
    int lk = (tid & 3) * 4;       // 0,4,8,12

    const float* Ap = A + (size_t)(m0 + lr) * K + lk;
    const float* Wp = W + (size_t)(n0 + lr) * K + lk;

    float acc[4][4] = {};

    for (int k0 = 0; k0 < K; k0 += 16) {
        float4 av = *(const float4*)(Ap + k0);
        float4 wv = *(const float4*)(Wp + k0);
        As[lk + 0][lr] = av.x; As[lk + 1][lr] = av.y;
        As[lk + 2][lr] = av.z; As[lk + 3][lr] = av.w;
        Ws[lk + 0][lr] = wv.x; Ws[lk + 1][lr] = wv.y;
        Ws[lk + 2][lr] = wv.z; Ws[lk + 3][lr] = wv.w;
        __syncthreads();

#pragma unroll
        for (int kk = 0; kk < 16; kk++) {
            float a[4], bv[4];
#pragma unroll
            for (int i = 0; i < 4; i++) a[i]  = As[kk][ty * 4 + i];
#pragma unroll
            for (int j = 0; j < 4; j++) bv[j] = Ws[kk][tx * 4 + j];
#pragma unroll
            for (int i = 0; i < 4; i++)
#pragma unroll
                for (int j = 0; j < 4; j++)
                    acc[i][j] += a[i] * bv[j];
        }
        __syncthreads();
    }

#pragma unroll
    for (int i = 0; i < 4; i++) {
        int m = m0 + ty * 4 + i;
#pragma unroll
        for (int j = 0; j < 4; j++) {
            int n = n0 + tx * 4 + j;
            float vv = acc[i][j] + bias[n];
            if (RELU)  vv = fmaxf(vv, 0.f);
            if (RESID) vv += R[(size_t)m * N + n];
            C[(size_t)m * N + n] = vv;
        }
    }
}

// ---------------------------------------------------------------------------
// LayerNorm over last dim (512). One block per row, 256 threads.
// ---------------------------------------------------------------------------
__global__ void ln_kernel(const float* __restrict__ x,
                          const float* __restrict__ w,
                          const float* __restrict__ b,
                          float* __restrict__ y)
{
    int r = blockIdx.x;
    int t = threadIdx.x;
    const float* xr = x + (size_t)r * DD;

    float v0 = xr[t], v1 = xr[t + 256];
    float s  = v0 + v1;
    float sq = v0 * v0 + v1 * v1;

#pragma unroll
    for (int off = 16; off; off >>= 1) {
        s  += __shfl_xor_sync(0xffffffffu, s,  off);
        sq += __shfl_xor_sync(0xffffffffu, sq, off);
    }
    __shared__ float sw[8], sqw[8];
    if ((t & 31) == 0) { sw[t >> 5] = s; sqw[t >> 5] = sq; }
    __syncthreads();
    s  = sw[0] + sw[1] + sw[2] + sw[3] + sw[4] + sw[5] + sw[6] + sw[7];
    sq = sqw[0] + sqw[1] + sqw[2] + sqw[3] + sqw[4] + sqw[5] + sqw[6] + sqw[7];

    float mean = s * (1.f / DD);
    float var  = sq * (1.f / DD) - mean * mean;
    float inv  = rsqrtf(var + 1e-5f);

    float* yr = y + (size_t)r * DD;
    yr[t]       = (v0 - mean) * inv * w[t]       + b[t];
    yr[t + 256] = (v1 - mean) * inv * w[t + 256] + b[t + 256];
}

// ---------------------------------------------------------------------------
// Host launcher
// ---------------------------------------------------------------------------
extern "C" void kernel_launch(void* const* d_in, const int* in_sizes, int n_in,
                              void* d_out, int out_size)
{
    const int*   x    = (const int*)  d_in[0];
    const float* emb  = (const float*)d_in[1];
    const float* pe   = (const float*)d_in[2];
    const float* Wq   = (const float*)d_in[3];
    const float* Wk   = (const float*)d_in[4];
    const float* Wv   = (const float*)d_in[5];
    const float* Wo   = (const float*)d_in[6];
    const float* bo   = (const float*)d_in[7];
    const float* ln1w = (const float*)d_in[8];
    const float* ln1b = (const float*)d_in[9];
    const float* W1   = (const float*)d_in[10];
    const float* b1   = (const float*)d_in[11];
    const float* W2   = (const float*)d_in[12];
    const float* b2   = (const float*)d_in[13];
    const float* ln2w = (const float*)d_in[14];
    const float* ln2b = (const float*)d_in[15];
    float* out = (float*)d_out;

    float *h, *q, *k, *v, *o, *t, *n1, *ff;
    cudaGetSymbolAddress((void**)&h,  g_h);
    cudaGetSymbolAddress((void**)&q,  g_q);
    cudaGetSymbolAddress((void**)&k,  g_k);
    cudaGetSymbolAddress((void**)&v,  g_v);
    cudaGetSymbolAddress((void**)&o,  g_o);
    cudaGetSymbolAddress((void**)&t,  g_t);
    cudaGetSymbolAddress((void**)&n1, g_n1);
    cudaGetSymbolAddress((void**)&ff, g_ff);

    embed_kernel<<<MM * DD / 256, 256>>>(x, emb, pe, h);

    for (int l = 0; l < LL; l++) {
        qkv_kernel<<<dim3(BB * HH, SS / 4), 256>>>(
            h, Wq + l * HD * HD, Wk + l * HD * HD, Wv + l * HD * HD, q, k, v);

        attn2_kernel<<<dim3(BB * HH, NQT), 256>>>(q, k, v, o);

        // t = o @ Wo^T + bo + h
        gemm_kernel<false, true><<<dim3(DD / 64, MM / 64), 256>>>(
            o, Wo + (size_t)l * DD * DD, bo + l * DD, h, t, MM, DD, DD);

        ln_kernel<<<MM, 256>>>(t, ln1w + l * DD, ln1b + l * DD, n1);

        // ff = relu(n1 @ W1^T + b1)
        gemm_kernel<true, false><<<dim3(FF / 64, MM / 64), 256>>>(
            n1, W1 + (size_t)l * FF * DD, b1 + l * FF, nullptr, ff, MM, FF, DD);

        // t = ff @ W2^T + b2 + n1
        gemm_kernel<false, true><<<dim3(DD / 64, MM / 64), 256>>>(
            ff, W2 + (size_t)l * DD * FF, b2 + l * DD, n1, t, MM, DD, FF);

        float* dst = (l == LL - 1) ? out : h;
        ln_kernel<<<MM, 256>>>(t, ln2w + l * DD, ln2b + l * DD, dst);
    }
}

// round 4
// speedup vs baseline: 3.0715x; 2.3554x over previous
#include <cuda_runtime.h>
#include <math.h>

// Problem constants
#define BB 32
#define SS 744
#define DD 512
#define HH 8
#define HD 64
#define LL 4
#define MM (BB*SS)     // 23808 = 64*372
#define FF (4*DD)      // 2048

#define QT 32          // queries per block (attention)
#define KT 32          // keys per tile (attention)
#define NQT ((SS + QT - 1) / QT)   // 24

// ---------------------------------------------------------------------------
// Scratch (device globals; no runtime allocation allowed)
// ---------------------------------------------------------------------------
__device__ float g_h [MM*DD];
__device__ float g_q [MM*DD];
__device__ float g_k [MM*DD];
__device__ float g_v [MM*DD];
__device__ float g_o [MM*DD];
__device__ float g_t [MM*DD];
__device__ float g_n1[MM*DD];
__device__ float g_ff[(size_t)MM*FF];

// ---------------------------------------------------------------------------
// Embedding: h[b,s,d] = emb[x[b,s],d]*sqrt(D) + pe[s,d]
// ---------------------------------------------------------------------------
__global__ void embed_kernel(const int* __restrict__ x,
                             const float* __restrict__ emb,
                             const float* __restrict__ pe,
                             float* __restrict__ h)
{
    int idx = blockIdx.x * 256 + threadIdx.x;       // < MM*DD
    int d   = idx & (DD - 1);
    int ms  = idx >> 9;                              // b*S + s
    int s   = ms % SS;
    int tok = x[ms];
    h[idx] = emb[tok * DD + d] * 22.627416997969522f + pe[s * DD + d];
}

// ---------------------------------------------------------------------------
// QKV v2: smem micro-GEMM. Weights transposed into smem (conflict-free
// lane-consecutive reads); X tile broadcast from smem.
// grid = (B*H, ceil(S/32), 2); block = 256.
// Block computes q/k/v[bh, s0:s0+32, e0:e0+32].
// ---------------------------------------------------------------------------
__global__ __launch_bounds__(256) void qkv2_kernel(
        const float* __restrict__ h,
        const float* __restrict__ Wq,
        const float* __restrict__ Wk,
        const float* __restrict__ Wv,
        float* __restrict__ q,
        float* __restrict__ k,
        float* __restrict__ v)
{
    __shared__ float Ws3[3][HD][33];   // [matrix][d][e_local], pad 33
    __shared__ float Xs[32][HD];       // [s_local][d]

    const int bh  = blockIdx.x;
    const int b   = bh >> 3;
    const int hh  = bh & 7;
    const int s0  = blockIdx.y * 32;
    const int e0  = blockIdx.z * 32;
    const int tid = threadIdx.x;

    // ---- load weights transposed: 3 matrices x 32 e-rows x 16 float4 ----
#pragma unroll
    for (int i = 0; i < 6; i++) {
        int idx = tid + i * 256;          // 0..1535
        int m   = idx >> 9;               // matrix 0..2
        int r   = idx & 511;
        int el  = r >> 4;                 // 0..31
        int d4  = (r & 15) * 4;
        const float* Wm = (m == 0) ? Wq : (m == 1) ? Wk : Wv;
        float4 a = *(const float4*)(Wm + (e0 + el) * HD + d4);
        Ws3[m][d4 + 0][el] = a.x;
        Ws3[m][d4 + 1][el] = a.y;
        Ws3[m][d4 + 2][el] = a.z;
        Ws3[m][d4 + 3][el] = a.w;
    }

    // ---- load X tile: 32 rows x 64 floats = 512 float4 ----
#pragma unroll
    for (int i = 0; i < 2; i++) {
        int f   = tid + i * 256;          // 0..511
        int row = f >> 4;
        int c4  = f & 15;
        int sg  = s0 + row; if (sg > SS - 1) sg = SS - 1;
        ((float4*)Xs[row])[c4] =
            *(const float4*)(h + (size_t)(b * SS + sg) * DD + hh * HD + c4 * 4);
    }
    __syncthreads();

    const int el = tid & 31;
    const int ty = tid >> 5;              // 0..7  (4 s-rows each)

    float aq[4] = {}, ak[4] = {}, av[4] = {};
#pragma unroll
    for (int d = 0; d < HD; d++) {
        float wq = Ws3[0][d][el];
        float wk = Ws3[1][d][el];
        float wv = Ws3[2][d][el];
#pragma unroll
        for (int r = 0; r < 4; r++) {
            float xv = Xs[ty * 4 + r][d];
            aq[r] += xv * wq;
            ak[r] += xv * wk;
            av[r] += xv * wv;
        }
    }

#pragma unroll
    for (int r = 0; r < 4; r++) {
        int s = s0 + ty * 4 + r;
        if (s < SS) {
            size_t oi = ((size_t)bh * SS + s) * HD + e0 + el;
            q[oi] = aq[r];
            k[oi] = ak[r];
            v[oi] = av[r];
        }
    }
}

// ---------------------------------------------------------------------------
// Attention v2: smem-tiled flash attention.
// grid = (B*H, NQT); block = 256 (8 warps). Each block: 32 queries.
// ---------------------------------------------------------------------------
__global__ __launch_bounds__(256) void attn2_kernel(
        const float* __restrict__ Q,
        const float* __restrict__ K,
        const float* __restrict__ V,
        float* __restrict__ O)
{
    __shared__ float Ks[HD][KT + 1];   // transposed K tile [d][j]
    __shared__ float Vs[KT][HD];       // V tile [j][e]
    __shared__ float Qs[QT][HD];       // Q tile [q][d]
    __shared__ float Ps[8][4][KT];     // per-warp softmax weights

    const int bh   = blockIdx.x;
    const int qt   = blockIdx.y;
    const int tid  = threadIdx.x;
    const int w    = tid >> 5;
    const int lane = tid & 31;

    const float* Qb = Q + (size_t)bh * SS * HD;
    const float* Kb = K + (size_t)bh * SS * HD;
    const float* Vb = V + (size_t)bh * SS * HD;

    // ---- load Q tile ----
    {
        const float4* Q4 = (const float4*)Qb;
#pragma unroll
        for (int i = 0; i < 2; i++) {
            int f   = tid + i * 256;
            int row = f >> 4;
            int c4  = f & 15;
            int sg  = qt * QT + row;
            if (sg > SS - 1) sg = SS - 1;
            ((float4*)Qs)[row * 16 + c4] = Q4[(size_t)sg * 16 + c4];
        }
    }

    float m[4], l[4], o0[4], o1[4];
#pragma unroll
    for (int q = 0; q < 4; q++) { m[q] = -INFINITY; l[q] = 0.f; o0[q] = 0.f; o1[q] = 0.f; }

    const int kj = tid >> 3;
    const int dg = (tid & 7) * 8;

    for (int kt = 0; kt < NQT; kt++) {
        int t0 = kt * KT;
        int nk = SS - t0; if (nk > KT) nk = KT;

        __syncthreads();

        {
            int tr = t0 + kj; if (tr > SS - 1) tr = SS - 1;
            const float4* kr = (const float4*)(Kb + (size_t)tr * HD + dg);
            float4 k0 = kr[0], k1 = kr[1];
            Ks[dg + 0][kj] = k0.x; Ks[dg + 1][kj] = k0.y;
            Ks[dg + 2][kj] = k0.z; Ks[dg + 3][kj] = k0.w;
            Ks[dg + 4][kj] = k1.x; Ks[dg + 5][kj] = k1.y;
            Ks[dg + 6][kj] = k1.z; Ks[dg + 7][kj] = k1.w;
            const float4* vr = (const float4*)(Vb + (size_t)tr * HD + dg);
            ((float4*)&Vs[kj][dg])[0] = vr[0];
            ((float4*)&Vs[kj][dg])[1] = vr[1];
        }
        __syncthreads();

        float s0 = 0.f, s1 = 0.f, s2 = 0.f, s3 = 0.f;
        const float4* q0p = (const float4*)Qs[w * 4 + 0];
        const float4* q1p = (const float4*)Qs[w * 4 + 1];
        const float4* q2p = (const float4*)Qs[w * 4 + 2];
        const float4* q3p = (const float4*)Qs[w * 4 + 3];
#pragma unroll
        for (int d4 = 0; d4 < 16; d4++) {
            float k0 = Ks[d4 * 4 + 0][lane];
            float k1 = Ks[d4 * 4 + 1][lane];
            float k2 = Ks[d4 * 4 + 2][lane];
            float k3 = Ks[d4 * 4 + 3][lane];
            float4 a;
            a = q0p[d4]; s0 += a.x*k0 + a.y*k1 + a.z*k2 + a.w*k3;
            a = q1p[d4]; s1 += a.x*k0 + a.y*k1 + a.z*k2 + a.w*k3;
            a = q2p[d4]; s2 += a.x*k0 + a.y*k1 + a.z*k2 + a.w*k3;
            a = q3p[d4]; s3 += a.x*k0 + a.y*k1 + a.z*k2 + a.w*k3;
        }
        float sc[4] = { s0 * 0.125f, s1 * 0.125f, s2 * 0.125f, s3 * 0.125f };
        if (lane >= nk) { sc[0] = sc[1] = sc[2] = sc[3] = -1e30f; }

#pragma unroll
        for (int q = 0; q < 4; q++) {
            float tmax = sc[q];
#pragma unroll
            for (int off = 16; off; off >>= 1)
                tmax = fmaxf(tmax, __shfl_xor_sync(0xffffffffu, tmax, off));
            float nm = fmaxf(m[q], tmax);
            float c  = __expf(m[q] - nm);
            float p  = __expf(sc[q] - nm);
            float ps = p;
#pragma unroll
            for (int off = 16; off; off >>= 1)
                ps += __shfl_xor_sync(0xffffffffu, ps, off);
            l[q]  = l[q] * c + ps;
            o0[q] *= c;  o1[q] *= c;
            m[q]  = nm;
            Ps[w][q][lane] = p;
        }
        __syncwarp();

#pragma unroll
        for (int j = 0; j < KT; j++) {
            float v0 = Vs[j][lane];
            float v1 = Vs[j][lane + 32];
            float p0 = Ps[w][0][j], p1 = Ps[w][1][j];
            float p2 = Ps[w][2][j], p3 = Ps[w][3][j];
            o0[0] += p0 * v0;  o1[0] += p0 * v1;
            o0[1] += p1 * v0;  o1[1] += p1 * v1;
            o0[2] += p2 * v0;  o1[2] += p2 * v1;
            o0[3] += p3 * v0;  o1[3] += p3 * v1;
        }
    }

    int b  = bh >> 3;
    int hh = bh & 7;
#pragma unroll
    for (int q = 0; q < 4; q++) {
        int s = qt * QT + w * 4 + q;
        if (s < SS) {
            float inv = 1.f / l[q];
            float* op = O + ((size_t)(b * SS + s)) * DD + hh * HD;
            op[lane]      = o0[q] * inv;
            op[lane + 32] = o1[q] * inv;
        }
    }
}

// ---------------------------------------------------------------------------
// Tiled SGEMM: C[m,n] = sum_k A[m,k]*W[n,k] (+bias[n]) (ReLU) (+R[m,n])
// BM=BN=64, BK=16, 256 threads, 4x4 microtile. Already at FFMA roofline.
// ---------------------------------------------------------------------------
template<bool RELU, bool RESID>
__global__ void gemm_kernel(const float* __restrict__ A,
                            const float* __restrict__ W,
                            const float* __restrict__ bias,
                            const float* __restrict__ R,
                            float* __restrict__ C,
                            int M, int N, int K)
{
    __shared__ float As[16][68];
    __shared__ float Ws[16][68];

    int tid = threadIdx.x;
    int tx  = tid & 15;
    int ty  = tid >> 4;
    int m0  = blockIdx.y * 64;
    int n0  = blockIdx.x * 64;

    int lr = tid >> 2;
    int lk = (tid & 3) * 4;

    const float* Ap = A + (size_t)(m0 + lr) * K + lk;
    const float* Wp = W + (size_t)(n0 + lr) * K + lk;

    float acc[4][4] = {};

    for (int k0 = 0; k0 < K; k0 += 16) {
        float4 av = *(const float4*)(Ap + k0);
        float4 wv = *(const float4*)(Wp + k0);
        As[lk + 0][lr] = av.x; As[lk + 1][lr] = av.y;
        As[lk + 2][lr] = av.z; As[lk + 3][lr] = av.w;
        Ws[lk + 0][lr] = wv.x; Ws[lk + 1][lr] = wv.y;
        Ws[lk + 2][lr] = wv.z; Ws[lk + 3][lr] = wv.w;
        __syncthreads();

#pragma unroll
        for (int kk = 0; kk < 16; kk++) {
            float a[4], bv[4];
#pragma unroll
            for (int i = 0; i < 4; i++) a[i]  = As[kk][ty * 4 + i];
#pragma unroll
            for (int j = 0; j < 4; j++) bv[j] = Ws[kk][tx * 4 + j];
#pragma unroll
            for (int i = 0; i < 4; i++)
#pragma unroll
                for (int j = 0; j < 4; j++)
                    acc[i][j] += a[i] * bv[j];
        }
        __syncthreads();
    }

#pragma unroll
    for (int i = 0; i < 4; i++) {
        int m = m0 + ty * 4 + i;
#pragma unroll
        for (int j = 0; j < 4; j++) {
            int n = n0 + tx * 4 + j;
            float vv = acc[i][j] + bias[n];
            if (RELU)  vv = fmaxf(vv, 0.f);
            if (RESID) vv += R[(size_t)m * N + n];
            C[(size_t)m * N + n] = vv;
        }
    }
}

// ---------------------------------------------------------------------------
// LayerNorm over last dim (512). One block per row, 256 threads.
// ---------------------------------------------------------------------------
__global__ void ln_kernel(const float* __restrict__ x,
                          const float* __restrict__ w,
                          const float* __restrict__ b,
                          float* __restrict__ y)
{
    int r = blockIdx.x;
    int t = threadIdx.x;
    const float* xr = x + (size_t)r * DD;

    float v0 = xr[t], v1 = xr[t + 256];
    float s  = v0 + v1;
    float sq = v0 * v0 + v1 * v1;

#pragma unroll
    for (int off = 16; off; off >>= 1) {
        s  += __shfl_xor_sync(0xffffffffu, s,  off);
        sq += __shfl_xor_sync(0xffffffffu, sq, off);
    }
    __shared__ float sw[8], sqw[8];
    if ((t & 31) == 0) { sw[t >> 5] = s; sqw[t >> 5] = sq; }
    __syncthreads();
    s  = sw[0] + sw[1] + sw[2] + sw[3] + sw[4] + sw[5] + sw[6] + sw[7];
    sq = sqw[0] + sqw[1] + sqw[2] + sqw[3] + sqw[4] + sqw[5] + sqw[6] + sqw[7];

    float mean = s * (1.f / DD);
    float var  = sq * (1.f / DD) - mean * mean;
    float inv  = rsqrtf(var + 1e-5f);

    float* yr = y + (size_t)r * DD;
    yr[t]       = (v0 - mean) * inv * w[t]       + b[t];
    yr[t + 256] = (v1 - mean) * inv * w[t + 256] + b[t + 256];
}

// ---------------------------------------------------------------------------
// Host launcher
// ---------------------------------------------------------------------------
extern "C" void kernel_launch(void* const* d_in, const int* in_sizes, int n_in,
                              void* d_out, int out_size)
{
    const int*   x    = (const int*)  d_in[0];
    const float* emb  = (const float*)d_in[1];
    const float* pe   = (const float*)d_in[2];
    const float* Wq   = (const float*)d_in[3];
    const float* Wk   = (const float*)d_in[4];
    const float* Wv   = (const float*)d_in[5];
    const float* Wo   = (const float*)d_in[6];
    const float* bo   = (const float*)d_in[7];
    const float* ln1w = (const float*)d_in[8];
    const float* ln1b = (const float*)d_in[9];
    const float* W1   = (const float*)d_in[10];
    const float* b1   = (const float*)d_in[11];
    const float* W2   = (const float*)d_in[12];
    const float* b2   = (const float*)d_in[13];
    const float* ln2w = (const float*)d_in[14];
    const float* ln2b = (const float*)d_in[15];
    float* out = (float*)d_out;

    float *h, *q, *k, *v, *o, *t, *n1, *ff;
    cudaGetSymbolAddress((void**)&h,  g_h);
    cudaGetSymbolAddress((void**)&q,  g_q);
    cudaGetSymbolAddress((void**)&k,  g_k);
    cudaGetSymbolAddress((void**)&v,  g_v);
    cudaGetSymbolAddress((void**)&o,  g_o);
    cudaGetSymbolAddress((void**)&t,  g_t);
    cudaGetSymbolAddress((void**)&n1, g_n1);
    cudaGetSymbolAddress((void**)&ff, g_ff);

    embed_kernel<<<MM * DD / 256, 256>>>(x, emb, pe, h);

    for (int l = 0; l < LL; l++) {
        qkv2_kernel<<<dim3(BB * HH, NQT, 2), 256>>>(
            h, Wq + l * HD * HD, Wk + l * HD * HD, Wv + l * HD * HD, q, k, v);

        attn2_kernel<<<dim3(BB * HH, NQT), 256>>>(q, k, v, o);

        // t = o @ Wo^T + bo + h
        gemm_kernel<false, true><<<dim3(DD / 64, MM / 64), 256>>>(
            o, Wo + (size_t)l * DD * DD, bo + l * DD, h, t, MM, DD, DD);

        ln_kernel<<<MM, 256>>>(t, ln1w + l * DD, ln1b + l * DD, n1);

        // ff = relu(n1 @ W1^T + b1)
        gemm_kernel<true, false><<<dim3(FF / 64, MM / 64), 256>>>(
            n1, W1 + (size_t)l * FF * DD, b1 + l * FF, nullptr, ff, MM, FF, DD);

        // t = ff @ W2^T + b2 + n1
        gemm_kernel<false, true><<<dim3(DD / 64, MM / 64), 256>>>(
            ff, W2 + (size_t)l * DD * FF, b2 + l * DD, n1, t, MM, DD, FF);

        float* dst = (l == LL - 1) ? out : h;
        ln_kernel<<<MM, 256>>>(t, ln2w + l * DD, ln2b + l * DD, dst);
    }
}

// round 6
// speedup vs baseline: 5.1275x; 1.6694x over previous
#include <cuda_runtime.h>
#include <cuda_bf16.h>
#include <math.h>
#include <stdint.h>

// Problem constants
#define BB 32
#define SS 744
#define DD 512
#define HH 8
#define HD 64
#define LL 4
#define MM (BB*SS)     // 23808 = 128*186
#define FF (4*DD)      // 2048

#define QT 32
#define KT 32
#define NQT ((SS + QT - 1) / QT)   // 24

__device__ __forceinline__ uint32_t smem_u32(const void* p) {
    uint32_t a;
    asm("{ .reg .u64 t; cvta.to.shared.u64 t, %1; cvt.u32.u64 %0, t; }" : "=r"(a) : "l"(p));
    return a;
}

// ---------------------------------------------------------------------------
// Scratch (device globals)
// ---------------------------------------------------------------------------
__device__ float g_h [MM*DD];
__device__ float g_q [MM*DD];
__device__ float g_k [MM*DD];
__device__ float g_v [MM*DD];
__device__ float g_t [MM*DD];
__device__ float g_n1[MM*DD];
// split-bf16 activations (hi, lo)
__device__ __nv_bfloat16 g_oh [MM*DD];
__device__ __nv_bfloat16 g_ol [MM*DD];
__device__ __nv_bfloat16 g_n1h[MM*DD];
__device__ __nv_bfloat16 g_n1l[MM*DD];
__device__ __nv_bfloat16 g_ffh[(size_t)MM*FF];
__device__ __nv_bfloat16 g_ffl[(size_t)MM*FF];
// split-bf16 weights
__device__ __nv_bfloat16 g_woh[LL*DD*DD];
__device__ __nv_bfloat16 g_wol[LL*DD*DD];
__device__ __nv_bfloat16 g_w1h[LL*FF*DD];
__device__ __nv_bfloat16 g_w1l[LL*FF*DD];
__device__ __nv_bfloat16 g_w2h[(size_t)LL*DD*FF];
__device__ __nv_bfloat16 g_w2l[(size_t)LL*DD*FF];

// ---------------------------------------------------------------------------
// fp32 -> split-bf16 (hi + lo)
// ---------------------------------------------------------------------------
__global__ void pack2_kernel(const float* __restrict__ in,
                             __nv_bfloat16* __restrict__ hi,
                             __nv_bfloat16* __restrict__ lo, int n)
{
    int i = blockIdx.x * 256 + threadIdx.x;
    if (i < n) {
        float v = in[i];
        __nv_bfloat16 hb = __float2bfloat16(v);
        hi[i] = hb;
        lo[i] = __float2bfloat16(v - __bfloat162float(hb));
    }
}

// ---------------------------------------------------------------------------
// Embedding
// ---------------------------------------------------------------------------
__global__ void embed_kernel(const int* __restrict__ x,
                             const float* __restrict__ emb,
                             const float* __restrict__ pe,
                             float* __restrict__ h)
{
    int idx = blockIdx.x * 256 + threadIdx.x;
    int d   = idx & (DD - 1);
    int ms  = idx >> 9;
    int s   = ms % SS;
    int tok = x[ms];
    h[idx] = emb[tok * DD + d] * 22.627416997969522f + pe[s * DD + d];
}

// ---------------------------------------------------------------------------
// QKV: smem micro-GEMM (fp32)
// ---------------------------------------------------------------------------
__global__ __launch_bounds__(256) void qkv2_kernel(
        const float* __restrict__ h,
        const float* __restrict__ Wq,
        const float* __restrict__ Wk,
        const float* __restrict__ Wv,
        float* __restrict__ q,
        float* __restrict__ k,
        float* __restrict__ v)
{
    __shared__ float Ws3[3][HD][33];
    __shared__ float Xs[32][HD];

    const int bh  = blockIdx.x;
    const int b   = bh >> 3;
    const int hh  = bh & 7;
    const int s0  = blockIdx.y * 32;
    const int e0  = blockIdx.z * 32;
    const int tid = threadIdx.x;

#pragma unroll
    for (int i = 0; i < 6; i++) {
        int idx = tid + i * 256;
        int m   = idx >> 9;
        int r   = idx & 511;
        int el  = r >> 4;
        int d4  = (r & 15) * 4;
        const float* Wm = (m == 0) ? Wq : (m == 1) ? Wk : Wv;
        float4 a = *(const float4*)(Wm + (e0 + el) * HD + d4);
        Ws3[m][d4 + 0][el] = a.x;
        Ws3[m][d4 + 1][el] = a.y;
        Ws3[m][d4 + 2][el] = a.z;
        Ws3[m][d4 + 3][el] = a.w;
    }
#pragma unroll
    for (int i = 0; i < 2; i++) {
        int f   = tid + i * 256;
        int row = f >> 4;
        int c4  = f & 15;
        int sg  = s0 + row; if (sg > SS - 1) sg = SS - 1;
        ((float4*)Xs[row])[c4] =
            *(const float4*)(h + (size_t)(b * SS + sg) * DD + hh * HD + c4 * 4);
    }
    __syncthreads();

    const int el = tid & 31;
    const int ty = tid >> 5;

    float aq[4] = {}, ak[4] = {}, av[4] = {};
#pragma unroll
    for (int d = 0; d < HD; d++) {
        float wq = Ws3[0][d][el];
        float wk = Ws3[1][d][el];
        float wv = Ws3[2][d][el];
#pragma unroll
        for (int r = 0; r < 4; r++) {
            float xv = Xs[ty * 4 + r][d];
            aq[r] += xv * wq;
            ak[r] += xv * wk;
            av[r] += xv * wv;
        }
    }
#pragma unroll
    for (int r = 0; r < 4; r++) {
        int s = s0 + ty * 4 + r;
        if (s < SS) {
            size_t oi = ((size_t)bh * SS + s) * HD + e0 + el;
            q[oi] = aq[r];
            k[oi] = ak[r];
            v[oi] = av[r];
        }
    }
}

// ---------------------------------------------------------------------------
// Attention: smem-tiled flash; epilogue writes split-bf16 O (hi, lo)
// ---------------------------------------------------------------------------
__global__ __launch_bounds__(256) void attn2_kernel(
        const float* __restrict__ Q,
        const float* __restrict__ K,
        const float* __restrict__ V,
        __nv_bfloat16* __restrict__ Oh,
        __nv_bfloat16* __restrict__ Ol)
{
    __shared__ float Ks[HD][KT + 1];
    __shared__ float Vs[KT][HD];
    __shared__ float Qs[QT][HD];
    __shared__ float Ps[8][4][KT];

    const int bh   = blockIdx.x;
    const int qt   = blockIdx.y;
    const int tid  = threadIdx.x;
    const int w    = tid >> 5;
    const int lane = tid & 31;

    const float* Qb = Q + (size_t)bh * SS * HD;
    const float* Kb = K + (size_t)bh * SS * HD;
    const float* Vb = V + (size_t)bh * SS * HD;

    {
        const float4* Q4 = (const float4*)Qb;
#pragma unroll
        for (int i = 0; i < 2; i++) {
            int f   = tid + i * 256;
            int row = f >> 4;
            int c4  = f & 15;
            int sg  = qt * QT + row;
            if (sg > SS - 1) sg = SS - 1;
            ((float4*)Qs)[row * 16 + c4] = Q4[(size_t)sg * 16 + c4];
        }
    }

    float m[4], l[4], o0[4], o1[4];
#pragma unroll
    for (int q = 0; q < 4; q++) { m[q] = -INFINITY; l[q] = 0.f; o0[q] = 0.f; o1[q] = 0.f; }

    const int kj = tid >> 3;
    const int dg = (tid & 7) * 8;

    for (int kt = 0; kt < NQT; kt++) {
        int t0 = kt * KT;
        int nk = SS - t0; if (nk > KT) nk = KT;

        __syncthreads();
        {
            int tr = t0 + kj; if (tr > SS - 1) tr = SS - 1;
            const float4* kr = (const float4*)(Kb + (size_t)tr * HD + dg);
            float4 k0 = kr[0], k1 = kr[1];
            Ks[dg + 0][kj] = k0.x; Ks[dg + 1][kj] = k0.y;
            Ks[dg + 2][kj] = k0.z; Ks[dg + 3][kj] = k0.w;
            Ks[dg + 4][kj] = k1.x; Ks[dg + 5][kj] = k1.y;
            Ks[dg + 6][kj] = k1.z; Ks[dg + 7][kj] = k1.w;
            const float4* vr = (const float4*)(Vb + (size_t)tr * HD + dg);
            ((float4*)&Vs[kj][dg])[0] = vr[0];
            ((float4*)&Vs[kj][dg])[1] = vr[1];
        }
        __syncthreads();

        float s0 = 0.f, s1 = 0.f, s2 = 0.f, s3 = 0.f;
        const float4* q0p = (const float4*)Qs[w * 4 + 0];
        const float4* q1p = (const float4*)Qs[w * 4 + 1];
        const float4* q2p = (const float4*)Qs[w * 4 + 2];
        const float4* q3p = (const float4*)Qs[w * 4 + 3];
#pragma unroll
        for (int d4 = 0; d4 < 16; d4++) {
            float k0 = Ks[d4 * 4 + 0][lane];
            float k1 = Ks[d4 * 4 + 1][lane];
            float k2 = Ks[d4 * 4 + 2][lane];
            float k3 = Ks[d4 * 4 + 3][lane];
            float4 a;
            a = q0p[d4]; s0 += a.x*k0 + a.y*k1 + a.z*k2 + a.w*k3;
            a = q1p[d4]; s1 += a.x*k0 + a.y*k1 + a.z*k2 + a.w*k3;
            a = q2p[d4]; s2 += a.x*k0 + a.y*k1 + a.z*k2 + a.w*k3;
            a = q3p[d4]; s3 += a.x*k0 + a.y*k1 + a.z*k2 + a.w*k3;
        }
        float sc[4] = { s0 * 0.125f, s1 * 0.125f, s2 * 0.125f, s3 * 0.125f };
        if (lane >= nk) { sc[0] = sc[1] = sc[2] = sc[3] = -1e30f; }

#pragma unroll
        for (int q = 0; q < 4; q++) {
            float tmax = sc[q];
#pragma unroll
            for (int off = 16; off; off >>= 1)
                tmax = fmaxf(tmax, __shfl_xor_sync(0xffffffffu, tmax, off));
            float nm = fmaxf(m[q], tmax);
            float c  = __expf(m[q] - nm);
            float p  = __expf(sc[q] - nm);
            float ps = p;
#pragma unroll
            for (int off = 16; off; off >>= 1)
                ps += __shfl_xor_sync(0xffffffffu, ps, off);
            l[q]  = l[q] * c + ps;
            o0[q] *= c;  o1[q] *= c;
            m[q]  = nm;
            Ps[w][q][lane] = p;
        }
        __syncwarp();

#pragma unroll
        for (int j = 0; j < KT; j++) {
            float v0 = Vs[j][lane];
            float v1 = Vs[j][lane + 32];
            float p0 = Ps[w][0][j], p1 = Ps[w][1][j];
            float p2 = Ps[w][2][j], p3 = Ps[w][3][j];
            o0[0] += p0 * v0;  o1[0] += p0 * v1;
            o0[1] += p1 * v0;  o1[1] += p1 * v1;
            o0[2] += p2 * v0;  o1[2] += p2 * v1;
            o0[3] += p3 * v0;  o1[3] += p3 * v1;
        }
    }

    int b  = bh >> 3;
    int hh = bh & 7;
#pragma unroll
    for (int q = 0; q < 4; q++) {
        int s = qt * QT + w * 4 + q;
        if (s < SS) {
            float inv = 1.f / l[q];
            size_t base = ((size_t)(b * SS + s)) * DD + hh * HD;
            float va = o0[q] * inv, vb = o1[q] * inv;
            __nv_bfloat16 ha = __float2bfloat16(va);
            __nv_bfloat16 hb = __float2bfloat16(vb);
            Oh[base + lane]      = ha;
            Oh[base + lane + 32] = hb;
            Ol[base + lane]      = __float2bfloat16(va - __bfloat162float(ha));
            Ol[base + lane + 32] = __float2bfloat16(vb - __bfloat162float(hb));
        }
    }
}

// ---------------------------------------------------------------------------
// Tensor-core GEMM via classic mma.sync (bf16 split-precision, fp32 accum).
// C[m,n] = sum_k A[m,k]*W[n,k], A/W given as (hi,lo) bf16 pairs.
// 3 products per k: Ah*Wh + Ah*Wl + Al*Wh.
// Block 128x128, 8 warps (2x4), warp tile 64x32 (4x4 m16n8k16). BK=32.
// M%128==0, N%128==0, K%32==0.
// ---------------------------------------------------------------------------
#define MMA_BF16(c, a, b) \
    asm volatile("mma.sync.aligned.m16n8k16.row.col.f32.bf16.bf16.f32 " \
        "{%0,%1,%2,%3}, {%4,%5,%6,%7}, {%8,%9}, {%0,%1,%2,%3};" \
        : "+f"((c)[0]), "+f"((c)[1]), "+f"((c)[2]), "+f"((c)[3]) \
        : "r"((a)[0]), "r"((a)[1]), "r"((a)[2]), "r"((a)[3]), \
          "r"((b)[0]), "r"((b)[1]))

#define LDMATRIX_X4(r, addr) \
    asm volatile("ldmatrix.sync.aligned.m8n8.x4.shared.b16 {%0,%1,%2,%3}, [%4];" \
        : "=r"((r)[0]), "=r"((r)[1]), "=r"((r)[2]), "=r"((r)[3]) : "r"(addr))

#define LDMATRIX_X2(r, addr) \
    asm volatile("ldmatrix.sync.aligned.m8n8.x2.shared.b16 {%0,%1}, [%2];" \
        : "=r"((r)[0]), "=r"((r)[1]) : "r"(addr))

template<bool RELU, bool RESID, bool PACKOUT>
__global__ __launch_bounds__(256, 2) void gemm_mma_kernel(
        const __nv_bfloat16* __restrict__ Ah, const __nv_bfloat16* __restrict__ Al,
        const __nv_bfloat16* __restrict__ Wh, const __nv_bfloat16* __restrict__ Wl,
        const float* __restrict__ bias, const float* __restrict__ R,
        float* __restrict__ Cf,
        __nv_bfloat16* __restrict__ Ch, __nv_bfloat16* __restrict__ Cl,
        int M, int N, int K)
{
    // stride 40 halves = 80B: rows hit 8 distinct 16B phases mod 128B
    __shared__ __align__(16) unsigned short sA[2][128][40];
    __shared__ __align__(16) unsigned short sW[2][128][40];

    const int tid  = threadIdx.x;
    const int lane = tid & 31;
    const int wid  = tid >> 5;
    const int wm   = (wid & 1) * 64;     // warp row offset
    const int wn   = (wid >> 1) * 32;    // warp col offset
    const int m0   = blockIdx.y * 128;
    const int n0   = blockIdx.x * 128;

    float acc[4][4][4] = {};

    // ldmatrix lane addressing (constant per thread)
    const int arow = lane & 15;
    const int acsel = (lane >> 4) * 8;
    const int l16  = lane & 15;
    const int brow = l16 & 7;
    const int bcsel = (l16 >> 3) * 8;

    for (int k0 = 0; k0 < K; k0 += 32) {
        __syncthreads();
        // ---- stage 128x32 chunks of A(hi,lo) and W(hi,lo) ----
#pragma unroll
        for (int t = 0; t < 2; t++) {
            int i   = tid + t * 256;        // 0..511
            int row = i >> 2;
            int c8  = (i & 3) * 8;
            *(uint4*)&sA[0][row][c8] = *(const uint4*)(Ah + (size_t)(m0 + row) * K + k0 + c8);
            *(uint4*)&sA[1][row][c8] = *(const uint4*)(Al + (size_t)(m0 + row) * K + k0 + c8);
            *(uint4*)&sW[0][row][c8] = *(const uint4*)(Wh + (size_t)(n0 + row) * K + k0 + c8);
            *(uint4*)&sW[1][row][c8] = *(const uint4*)(Wl + (size_t)(n0 + row) * K + k0 + c8);
        }
        __syncthreads();

#pragma unroll
        for (int ks = 0; ks < 2; ks++) {
            const int kcol = ks * 16;

            // B fragments (4 n8-tiles, hi & lo)
            uint32_t bh[4][2], bl[4][2];
#pragma unroll
            for (int nt = 0; nt < 4; nt++) {
                uint32_t a0 = smem_u32(&sW[0][wn + nt * 8 + brow][kcol + bcsel]);
                LDMATRIX_X2(bh[nt], a0);
                uint32_t a1 = smem_u32(&sW[1][wn + nt * 8 + brow][kcol + bcsel]);
                LDMATRIX_X2(bl[nt], a1);
            }

#pragma unroll
            for (int mt = 0; mt < 4; mt++) {
                uint32_t ahf[4], alf[4];
                uint32_t aa0 = smem_u32(&sA[0][wm + mt * 16 + arow][kcol + acsel]);
                LDMATRIX_X4(ahf, aa0);
                uint32_t aa1 = smem_u32(&sA[1][wm + mt * 16 + arow][kcol + acsel]);
                LDMATRIX_X4(alf, aa1);
#pragma unroll
                for (int nt = 0; nt < 4; nt++) {
                    MMA_BF16(acc[mt][nt], ahf, bh[nt]);
                    MMA_BF16(acc[mt][nt], ahf, bl[nt]);
                    MMA_BF16(acc[mt][nt], alf, bh[nt]);
                }
            }
        }
    }

    // ---- epilogue ----
    const int r4 = lane >> 2;
    const int c2 = (lane & 3) * 2;
#pragma unroll
    for (int mt = 0; mt < 4; mt++) {
#pragma unroll
        for (int nt = 0; nt < 4; nt++) {
#pragma unroll
            for (int e = 0; e < 4; e++) {
                int mg = m0 + wm + mt * 16 + r4 + (e >> 1) * 8;
                int ng = n0 + wn + nt * 8 + c2 + (e & 1);
                float v = acc[mt][nt][e] + bias[ng];
                if (RELU)  v = fmaxf(v, 0.f);
                if (RESID) v += R[(size_t)mg * N + ng];
                if (PACKOUT) {
                    __nv_bfloat16 hb = __float2bfloat16(v);
                    Ch[(size_t)mg * N + ng] = hb;
                    Cl[(size_t)mg * N + ng] = __float2bfloat16(v - __bfloat162float(hb));
                } else {
                    Cf[(size_t)mg * N + ng] = v;
                }
            }
        }
    }
}

// ---------------------------------------------------------------------------
// LayerNorm; optionally also writes split-bf16 copy
// ---------------------------------------------------------------------------
template<bool PACK>
__global__ void ln_kernel(const float* __restrict__ x,
                          const float* __restrict__ w,
                          const float* __restrict__ b,
                          float* __restrict__ y,
                          __nv_bfloat16* __restrict__ yh,
                          __nv_bfloat16* __restrict__ yl)
{
    int r = blockIdx.x;
    int t = threadIdx.x;
    const float* xr = x + (size_t)r * DD;

    float v0 = xr[t], v1 = xr[t + 256];
    float s  = v0 + v1;
    float sq = v0 * v0 + v1 * v1;

#pragma unroll
    for (int off = 16; off; off >>= 1) {
        s  += __shfl_xor_sync(0xffffffffu, s,  off);
        sq += __shfl_xor_sync(0xffffffffu, sq, off);
    }
    __shared__ float sw[8], sqw[8];
    if ((t & 31) == 0) { sw[t >> 5] = s; sqw[t >> 5] = sq; }
    __syncthreads();
    s  = sw[0] + sw[1] + sw[2] + sw[3] + sw[4] + sw[5] + sw[6] + sw[7];
    sq = sqw[0] + sqw[1] + sqw[2] + sqw[3] + sqw[4] + sqw[5] + sqw[6] + sqw[7];

    float mean = s * (1.f / DD);
    float var  = sq * (1.f / DD) - mean * mean;
    float inv  = rsqrtf(var + 1e-5f);

    float r0 = (v0 - mean) * inv * w[t]       + b[t];
    float r1 = (v1 - mean) * inv * w[t + 256] + b[t + 256];
    float* yr = y + (size_t)r * DD;
    yr[t]       = r0;
    yr[t + 256] = r1;
    if (PACK) {
        size_t base = (size_t)r * DD;
        __nv_bfloat16 h0 = __float2bfloat16(r0);
        __nv_bfloat16 h1 = __float2bfloat16(r1);
        yh[base + t]       = h0;
        yh[base + t + 256] = h1;
        yl[base + t]       = __float2bfloat16(r0 - __bfloat162float(h0));
        yl[base + t + 256] = __float2bfloat16(r1 - __bfloat162float(h1));
    }
}

// ---------------------------------------------------------------------------
// Host launcher
// ---------------------------------------------------------------------------
extern "C" void kernel_launch(void* const* d_in, const int* in_sizes, int n_in,
                              void* d_out, int out_size)
{
    const int*   x    = (const int*)  d_in[0];
    const float* emb  = (const float*)d_in[1];
    const float* pe   = (const float*)d_in[2];
    const float* Wq   = (const float*)d_in[3];
    const float* Wk   = (const float*)d_in[4];
    const float* Wv   = (const float*)d_in[5];
    const float* Wo   = (const float*)d_in[6];
    const float* bo   = (const float*)d_in[7];
    const float* ln1w = (const float*)d_in[8];
    const float* ln1b = (const float*)d_in[9];
    const float* W1   = (const float*)d_in[10];
    const float* b1   = (const float*)d_in[11];
    const float* W2   = (const float*)d_in[12];
    const float* b2   = (const float*)d_in[13];
    const float* ln2w = (const float*)d_in[14];
    const float* ln2b = (const float*)d_in[15];
    float* out = (float*)d_out;

    float *h, *q, *k, *v, *t, *n1;
    __nv_bfloat16 *oh, *ol, *n1h, *n1l, *ffh, *ffl;
    __nv_bfloat16 *woh, *wol, *w1h, *w1l, *w2h, *w2l;
    cudaGetSymbolAddress((void**)&h,   g_h);
    cudaGetSymbolAddress((void**)&q,   g_q);
    cudaGetSymbolAddress((void**)&k,   g_k);
    cudaGetSymbolAddress((void**)&v,   g_v);
    cudaGetSymbolAddress((void**)&t,   g_t);
    cudaGetSymbolAddress((void**)&n1,  g_n1);
    cudaGetSymbolAddress((void**)&oh,  g_oh);
    cudaGetSymbolAddress((void**)&ol,  g_ol);
    cudaGetSymbolAddress((void**)&n1h, g_n1h);
    cudaGetSymbolAddress((void**)&n1l, g_n1l);
    cudaGetSymbolAddress((void**)&ffh, g_ffh);
    cudaGetSymbolAddress((void**)&ffl, g_ffl);
    cudaGetSymbolAddress((void**)&woh, g_woh);
    cudaGetSymbolAddress((void**)&wol, g_wol);
    cudaGetSymbolAddress((void**)&w1h, g_w1h);
    cudaGetSymbolAddress((void**)&w1l, g_w1l);
    cudaGetSymbolAddress((void**)&w2h, g_w2h);
    cudaGetSymbolAddress((void**)&w2l, g_w2l);

    // split-pack weights (cheap, deterministic, graph-capturable)
    pack2_kernel<<<(LL*DD*DD + 255) / 256, 256>>>(Wo, woh, wol, LL*DD*DD);
    pack2_kernel<<<(LL*FF*DD + 255) / 256, 256>>>(W1, w1h, w1l, LL*FF*DD);
    pack2_kernel<<<(LL*DD*FF + 255) / 256, 256>>>(W2, w2h, w2l, LL*DD*FF);

    embed_kernel<<<MM * DD / 256, 256>>>(x, emb, pe, h);

    for (int l = 0; l < LL; l++) {
        qkv2_kernel<<<dim3(BB * HH, NQT, 2), 256>>>(
            h, Wq + l * HD * HD, Wk + l * HD * HD, Wv + l * HD * HD, q, k, v);

        attn2_kernel<<<dim3(BB * HH, NQT), 256>>>(q, k, v, oh, ol);

        // t = o @ Wo^T + bo + h   (fp32 out)
        gemm_mma_kernel<false, true, false><<<dim3(DD / 128, MM / 128), 256>>>(
            oh, ol, woh + (size_t)l * DD * DD, wol + (size_t)l * DD * DD,
            bo + l * DD, h, t, nullptr, nullptr, MM, DD, DD);

        ln_kernel<true><<<MM, 256>>>(t, ln1w + l * DD, ln1b + l * DD, n1, n1h, n1l);

        // ff = relu(n1 @ W1^T + b1)  (split-bf16 out)
        gemm_mma_kernel<true, false, true><<<dim3(FF / 128, MM / 128), 256>>>(
            n1h, n1l, w1h + (size_t)l * FF * DD, w1l + (size_t)l * FF * DD,
            b1 + l * FF, nullptr, nullptr, ffh, ffl, MM, FF, DD);

        // t = ff @ W2^T + b2 + n1  (fp32 out)
        gemm_mma_kernel<false, true, false><<<dim3(DD / 128, MM / 128), 256>>>(
            ffh, ffl, w2h + (size_t)l * DD * FF, w2l + (size_t)l * DD * FF,
            b2 + l * DD, n1, t, nullptr, nullptr, MM, DD, FF);

        float* dst = (l == LL - 1) ? out : h;
        ln_kernel<false><<<MM, 256>>>(t, ln2w + l * DD, ln2b + l * DD, dst, nullptr, nullptr);
    }
}

// round 11
// speedup vs baseline: 5.4355x; 1.0601x over previous
#include <cuda_runtime.h>
#include <cuda_bf16.h>
#include <math.h>
#include <stdint.h>

// Problem constants
#define BB 32
#define SS 744
#define DD 512
#define HH 8
#define HD 64
#define LL 4
#define MM (BB*SS)     // 23808 = 128*186
#define FF (4*DD)      // 2048

#define QT 32
#define KT 32
#define NQT ((SS + QT - 1) / QT)   // 24

__device__ __forceinline__ uint32_t smem_u32(const void* p) {
    uint32_t a;
    asm("{ .reg .u64 t; cvta.to.shared.u64 t, %1; cvt.u32.u64 %0, t; }" : "=r"(a) : "l"(p));
    return a;
}
__device__ __forceinline__ void cp16(uint32_t dst, const void* src) {
    asm volatile("cp.async.cg.shared.global [%0], [%1], 16;" :: "r"(dst), "l"(src) : "memory");
}
#define CP_COMMIT() asm volatile("cp.async.commit_group;" ::: "memory")
#define CP_WAIT1()  asm volatile("cp.async.wait_group 1;" ::: "memory")
#define CP_WAIT0()  asm volatile("cp.async.wait_group 0;" ::: "memory")

// ---------------------------------------------------------------------------
// Scratch (device globals)
// ---------------------------------------------------------------------------
__device__ float g_h [MM*DD];
__device__ float g_q [MM*DD];
__device__ float g_k [MM*DD];
__device__ float g_v [MM*DD];
__device__ float g_t [MM*DD];
__device__ float g_n1[MM*DD];
// split-bf16 activations (hi, lo)
__device__ __nv_bfloat16 g_oh [MM*DD];
__device__ __nv_bfloat16 g_ol [MM*DD];
__device__ __nv_bfloat16 g_n1h[MM*DD];
__device__ __nv_bfloat16 g_n1l[MM*DD];
__device__ __nv_bfloat16 g_ffh[(size_t)MM*FF];
__device__ __nv_bfloat16 g_ffl[(size_t)MM*FF];
// split-bf16 weights
__device__ __nv_bfloat16 g_woh[LL*DD*DD];
__device__ __nv_bfloat16 g_wol[LL*DD*DD];
__device__ __nv_bfloat16 g_w1h[LL*FF*DD];
__device__ __nv_bfloat16 g_w1l[LL*FF*DD];
__device__ __nv_bfloat16 g_w2h[(size_t)LL*DD*FF];
__device__ __nv_bfloat16 g_w2l[(size_t)LL*DD*FF];

// ---------------------------------------------------------------------------
// fp32 -> split-bf16 (hi + lo)
// ---------------------------------------------------------------------------
__global__ void pack2_kernel(const float* __restrict__ in,
                             __nv_bfloat16* __restrict__ hi,
                             __nv_bfloat16* __restrict__ lo, int n)
{
    int i = blockIdx.x * 256 + threadIdx.x;
    if (i < n) {
        float v = in[i];
        __nv_bfloat16 hb = __float2bfloat16(v);
        hi[i] = hb;
        lo[i] = __float2bfloat16(v - __bfloat162float(hb));
    }
}

// ---------------------------------------------------------------------------
// Embedding
// ---------------------------------------------------------------------------
__global__ void embed_kernel(const int* __restrict__ x,
                             const float* __restrict__ emb,
                             const float* __restrict__ pe,
                             float* __restrict__ h)
{
    int idx = blockIdx.x * 256 + threadIdx.x;
    int d   = idx & (DD - 1);
    int ms  = idx >> 9;
    int s   = ms % SS;
    int tok = x[ms];
    h[idx] = emb[tok * DD + d] * 22.627416997969522f + pe[s * DD + d];
}

// ---------------------------------------------------------------------------
// QKV: smem micro-GEMM (fp32)
// ---------------------------------------------------------------------------
__global__ __launch_bounds__(256) void qkv2_kernel(
        const float* __restrict__ h,
        const float* __restrict__ Wq,
        const float* __restrict__ Wk,
        const float* __restrict__ Wv,
        float* __restrict__ q,
        float* __restrict__ k,
        float* __restrict__ v)
{
    __shared__ float Ws3[3][HD][33];
    __shared__ float Xs[32][HD];

    const int bh  = blockIdx.x;
    const int b   = bh >> 3;
    const int hh  = bh & 7;
    const int s0  = blockIdx.y * 32;
    const int e0  = blockIdx.z * 32;
    const int tid = threadIdx.x;

#pragma unroll
    for (int i = 0; i < 6; i++) {
        int idx = tid + i * 256;
        int m   = idx >> 9;
        int r   = idx & 511;
        int el  = r >> 4;
        int d4  = (r & 15) * 4;
        const float* Wm = (m == 0) ? Wq : (m == 1) ? Wk : Wv;
        float4 a = *(const float4*)(Wm + (e0 + el) * HD + d4);
        Ws3[m][d4 + 0][el] = a.x;
        Ws3[m][d4 + 1][el] = a.y;
        Ws3[m][d4 + 2][el] = a.z;
        Ws3[m][d4 + 3][el] = a.w;
    }
#pragma unroll
    for (int i = 0; i < 2; i++) {
        int f   = tid + i * 256;
        int row = f >> 4;
        int c4  = f & 15;
        int sg  = s0 + row; if (sg > SS - 1) sg = SS - 1;
        ((float4*)Xs[row])[c4] =
            *(const float4*)(h + (size_t)(b * SS + sg) * DD + hh * HD + c4 * 4);
    }
    __syncthreads();

    const int el = tid & 31;
    const int ty = tid >> 5;

    float aq[4] = {}, ak[4] = {}, av[4] = {};
#pragma unroll
    for (int d = 0; d < HD; d++) {
        float wq = Ws3[0][d][el];
        float wk = Ws3[1][d][el];
        float wv = Ws3[2][d][el];
#pragma unroll
        for (int r = 0; r < 4; r++) {
            float xv = Xs[ty * 4 + r][d];
            aq[r] += xv * wq;
            ak[r] += xv * wk;
            av[r] += xv * wv;
        }
    }
#pragma unroll
    for (int r = 0; r < 4; r++) {
        int s = s0 + ty * 4 + r;
        if (s < SS) {
            size_t oi = ((size_t)bh * SS + s) * HD + e0 + el;
            q[oi] = aq[r];
            k[oi] = ak[r];
            v[oi] = av[r];
        }
    }
}

// ---------------------------------------------------------------------------
// Attention: smem-tiled flash; epilogue writes split-bf16 O (hi, lo)
// ---------------------------------------------------------------------------
__global__ __launch_bounds__(256) void attn2_kernel(
        const float* __restrict__ Q,
        const float* __restrict__ K,
        const float* __restrict__ V,
        __nv_bfloat16* __restrict__ Oh,
        __nv_bfloat16* __restrict__ Ol)
{
    __shared__ float Ks[HD][KT + 1];
    __shared__ float Vs[KT][HD];
    __shared__ float Qs[QT][HD];
    __shared__ float Ps[8][4][KT];

    const int bh   = blockIdx.x;
    const int qt   = blockIdx.y;
    const int tid  = threadIdx.x;
    const int w    = tid >> 5;
    const int lane = tid & 31;

    const float* Qb = Q + (size_t)bh * SS * HD;
    const float* Kb = K + (size_t)bh * SS * HD;
    const float* Vb = V + (size_t)bh * SS * HD;

    {
        const float4* Q4 = (const float4*)Qb;
#pragma unroll
        for (int i = 0; i < 2; i++) {
            int f   = tid + i * 256;
            int row = f >> 4;
            int c4  = f & 15;
            int sg  = qt * QT + row;
            if (sg > SS - 1) sg = SS - 1;
            ((float4*)Qs)[row * 16 + c4] = Q4[(size_t)sg * 16 + c4];
        }
    }

    float m[4], l[4], o0[4], o1[4];
#pragma unroll
    for (int q = 0; q < 4; q++) { m[q] = -INFINITY; l[q] = 0.f; o0[q] = 0.f; o1[q] = 0.f; }

    const int kj = tid >> 3;
    const int dg = (tid & 7) * 8;

    for (int kt = 0; kt < NQT; kt++) {
        int t0 = kt * KT;
        int nk = SS - t0; if (nk > KT) nk = KT;

        __syncthreads();
        {
            int tr = t0 + kj; if (tr > SS - 1) tr = SS - 1;
            const float4* kr = (const float4*)(Kb + (size_t)tr * HD + dg);
            float4 k0 = kr[0], k1 = kr[1];
            Ks[dg + 0][kj] = k0.x; Ks[dg + 1][kj] = k0.y;
            Ks[dg + 2][kj] = k0.z; Ks[dg + 3][kj] = k0.w;
            Ks[dg + 4][kj] = k1.x; Ks[dg + 5][kj] = k1.y;
            Ks[dg + 6][kj] = k1.z; Ks[dg + 7][kj] = k1.w;
            const float4* vr = (const float4*)(Vb + (size_t)tr * HD + dg);
            ((float4*)&Vs[kj][dg])[0] = vr[0];
            ((float4*)&Vs[kj][dg])[1] = vr[1];
        }
        __syncthreads();

        float s0 = 0.f, s1 = 0.f, s2 = 0.f, s3 = 0.f;
        const float4* q0p = (const float4*)Qs[w * 4 + 0];
        const float4* q1p = (const float4*)Qs[w * 4 + 1];
        const float4* q2p = (const float4*)Qs[w * 4 + 2];
        const float4* q3p = (const float4*)Qs[w * 4 + 3];
#pragma unroll
        for (int d4 = 0; d4 < 16; d4++) {
            float k0 = Ks[d4 * 4 + 0][lane];
            float k1 = Ks[d4 * 4 + 1][lane];
            float k2 = Ks[d4 * 4 + 2][lane];
            float k3 = Ks[d4 * 4 + 3][lane];
            float4 a;
            a = q0p[d4]; s0 += a.x*k0 + a.y*k1 + a.z*k2 + a.w*k3;
            a = q1p[d4]; s1 += a.x*k0 + a.y*k1 + a.z*k2 + a.w*k3;
            a = q2p[d4]; s2 += a.x*k0 + a.y*k1 + a.z*k2 + a.w*k3;
            a = q3p[d4]; s3 += a.x*k0 + a.y*k1 + a.z*k2 + a.w*k3;
        }
        float sc[4] = { s0 * 0.125f, s1 * 0.125f, s2 * 0.125f, s3 * 0.125f };
        if (lane >= nk) { sc[0] = sc[1] = sc[2] = sc[3] = -1e30f; }

#pragma unroll
        for (int q = 0; q < 4; q++) {
            float tmax = sc[q];
#pragma unroll
            for (int off = 16; off; off >>= 1)
                tmax = fmaxf(tmax, __shfl_xor_sync(0xffffffffu, tmax, off));
            float nm = fmaxf(m[q], tmax);
            float c  = __expf(m[q] - nm);
            float p  = __expf(sc[q] - nm);
            float ps = p;
#pragma unroll
            for (int off = 16; off; off >>= 1)
                ps += __shfl_xor_sync(0xffffffffu, ps, off);
            l[q]  = l[q] * c + ps;
            o0[q] *= c;  o1[q] *= c;
            m[q]  = nm;
            Ps[w][q][lane] = p;
        }
        __syncwarp();

#pragma unroll
        for (int j = 0; j < KT; j++) {
            float v0 = Vs[j][lane];
            float v1 = Vs[j][lane + 32];
            float p0 = Ps[w][0][j], p1 = Ps[w][1][j];
            float p2 = Ps[w][2][j], p3 = Ps[w][3][j];
            o0[0] += p0 * v0;  o1[0] += p0 * v1;
            o0[1] += p1 * v0;  o1[1] += p1 * v1;
            o0[2] += p2 * v0;  o1[2] += p2 * v1;
            o0[3] += p3 * v0;  o1[3] += p3 * v1;
        }
    }

    int b  = bh >> 3;
    int hh = bh & 7;
#pragma unroll
    for (int q = 0; q < 4; q++) {
        int s = qt * QT + w * 4 + q;
        if (s < SS) {
            float inv = 1.f / l[q];
            size_t base = ((size_t)(b * SS + s)) * DD + hh * HD;
            float va = o0[q] * inv, vb = o1[q] * inv;
            __nv_bfloat16 ha = __float2bfloat16(va);
            __nv_bfloat16 hb = __float2bfloat16(vb);
            Oh[base + lane]      = ha;
            Oh[base + lane + 32] = hb;
            Ol[base + lane]      = __float2bfloat16(va - __bfloat162float(ha));
            Ol[base + lane + 32] = __float2bfloat16(vb - __bfloat162float(hb));
        }
    }
}

// ---------------------------------------------------------------------------
// Tensor-core GEMM via mma.sync, split-bf16, cp.async double-buffered.
// C[m,n] = sum_k A[m,k]*W[n,k]; 3 products: Ah*Wh + Ah*Wl + Al*Wh.
// Block 128x128, 8 warps (2x4), warp tile 64x32 (4x4 m16n8k16). BK=32.
// Dyn smem: 2 stages x (Ah|Al|Wh|Wl each 128x40 halves) = 81920 B.
// ---------------------------------------------------------------------------
#define MMA_BF16(c, a, b) \
    asm volatile("mma.sync.aligned.m16n8k16.row.col.f32.bf16.bf16.f32 " \
        "{%0,%1,%2,%3}, {%4,%5,%6,%7}, {%8,%9}, {%0,%1,%2,%3};" \
        : "+f"((c)[0]), "+f"((c)[1]), "+f"((c)[2]), "+f"((c)[3]) \
        : "r"((a)[0]), "r"((a)[1]), "r"((a)[2]), "r"((a)[3]), \
          "r"((b)[0]), "r"((b)[1]))

#define LDMATRIX_X4(r, addr) \
    asm volatile("ldmatrix.sync.aligned.m8n8.x4.shared.b16 {%0,%1,%2,%3}, [%4];" \
        : "=r"((r)[0]), "=r"((r)[1]), "=r"((r)[2]), "=r"((r)[3]) : "r"(addr))

#define LDMATRIX_X2(r, addr) \
    asm volatile("ldmatrix.sync.aligned.m8n8.x2.shared.b16 {%0,%1}, [%2];" \
        : "=r"((r)[0]), "=r"((r)[1]) : "r"(addr))

#define G_ROWB   80                      // 40 halves per row
#define G_MAT    10240                   // 128 * 80
#define G_STAGE  40960                   // 4 matrices
#define G_SMEM   81920                   // 2 stages

template<bool RELU, bool RESID, bool PACKOUT>
__global__ __launch_bounds__(256, 2) void gemm_mma_kernel(
        const __nv_bfloat16* __restrict__ Ah, const __nv_bfloat16* __restrict__ Al,
        const __nv_bfloat16* __restrict__ Wh, const __nv_bfloat16* __restrict__ Wl,
        const float* __restrict__ bias, const float* __restrict__ R,
        float* __restrict__ Cf,
        __nv_bfloat16* __restrict__ Ch, __nv_bfloat16* __restrict__ Cl,
        int M, int N, int K)
{
    extern __shared__ char dsm[];
    const uint32_t sb = smem_u32(dsm);

    const int tid  = threadIdx.x;
    const int lane = tid & 31;
    const int wid  = tid >> 5;
    const int wm   = (wid & 1) * 64;
    const int wn   = (wid >> 1) * 32;
    const int m0   = blockIdx.y * 128;
    const int n0   = blockIdx.x * 128;

    float acc[4][4][4] = {};

    // prefetch addressing (per thread: 2 iters x 4 matrices, 16B each)
    const int prow0 = tid >> 2;           // rows 0..63   (t=0)
    const int prow1 = prow0 + 64;         // rows 64..127 (t=1)
    const int pc8   = (tid & 3) * 8;      // half offset in chunk
    const uint32_t pdst0 = (uint32_t)(prow0 * G_ROWB + pc8 * 2);
    const uint32_t pdst1 = (uint32_t)(prow1 * G_ROWB + pc8 * 2);

    // ldmatrix lane addressing
    const int arow  = lane & 15;
    const int acsel = (lane >> 4) * 8;
    const int l16   = lane & 15;
    const int brow  = l16 & 7;
    const int bcsel = (l16 >> 3) * 8;

    const int nchunk = K >> 5;

    // prefetch chunk kc into stage st
    auto prefetch = [&](int kc, int st) {
        const int k0 = kc << 5;
        const uint32_t s0 = sb + st * G_STAGE;
        cp16(s0 + 0*G_MAT + pdst0, Ah + (size_t)(m0 + prow0) * K + k0 + pc8);
        cp16(s0 + 0*G_MAT + pdst1, Ah + (size_t)(m0 + prow1) * K + k0 + pc8);
        cp16(s0 + 1*G_MAT + pdst0, Al + (size_t)(m0 + prow0) * K + k0 + pc8);
        cp16(s0 + 1*G_MAT + pdst1, Al + (size_t)(m0 + prow1) * K + k0 + pc8);
        cp16(s0 + 2*G_MAT + pdst0, Wh + (size_t)(n0 + prow0) * K + k0 + pc8);
        cp16(s0 + 2*G_MAT + pdst1, Wh + (size_t)(n0 + prow1) * K + k0 + pc8);
        cp16(s0 + 3*G_MAT + pdst0, Wl + (size_t)(n0 + prow0) * K + k0 + pc8);
        cp16(s0 + 3*G_MAT + pdst1, Wl + (size_t)(n0 + prow1) * K + k0 + pc8);
    };

    prefetch(0, 0);
    CP_COMMIT();

    for (int kc = 0; kc < nchunk; kc++) {
        const int st = kc & 1;
        if (kc + 1 < nchunk) {
            prefetch(kc + 1, st ^ 1);
            CP_COMMIT();
            CP_WAIT1();
        } else {
            CP_WAIT0();
        }
        __syncthreads();

        const uint32_t s0 = sb + st * G_STAGE;
#pragma unroll
        for (int ks = 0; ks < 2; ks++) {
            const int kcol = ks * 16;

            uint32_t bh[4][2], bl[4][2];
#pragma unroll
            for (int nt = 0; nt < 4; nt++) {
                uint32_t r = (uint32_t)((wn + nt * 8 + brow) * G_ROWB + (kcol + bcsel) * 2);
                LDMATRIX_X2(bh[nt], s0 + 2*G_MAT + r);
                LDMATRIX_X2(bl[nt], s0 + 3*G_MAT + r);
            }
#pragma unroll
            for (int mt = 0; mt < 4; mt++) {
                uint32_t ahf[4], alf[4];
                uint32_t r = (uint32_t)((wm + mt * 16 + arow) * G_ROWB + (kcol + acsel) * 2);
                LDMATRIX_X4(ahf, s0 + 0*G_MAT + r);
                LDMATRIX_X4(alf, s0 + 1*G_MAT + r);
#pragma unroll
                for (int nt = 0; nt < 4; nt++) {
                    MMA_BF16(acc[mt][nt], ahf, bh[nt]);
                    MMA_BF16(acc[mt][nt], ahf, bl[nt]);
                    MMA_BF16(acc[mt][nt], alf, bh[nt]);
                }
            }
        }
        __syncthreads();
    }

    // ---- epilogue ----
    const int r4 = lane >> 2;
    const int c2 = (lane & 3) * 2;
#pragma unroll
    for (int mt = 0; mt < 4; mt++) {
#pragma unroll
        for (int nt = 0; nt < 4; nt++) {
#pragma unroll
            for (int e = 0; e < 4; e++) {
                int mg = m0 + wm + mt * 16 + r4 + (e >> 1) * 8;
                int ng = n0 + wn + nt * 8 + c2 + (e & 1);
                float v = acc[mt][nt][e] + bias[ng];
                if (RELU)  v = fmaxf(v, 0.f);
                if (RESID) v += R[(size_t)mg * N + ng];
                if (PACKOUT) {
                    __nv_bfloat16 hb = __float2bfloat16(v);
                    Ch[(size_t)mg * N + ng] = hb;
                    Cl[(size_t)mg * N + ng] = __float2bfloat16(v - __bfloat162float(hb));
                } else {
                    Cf[(size_t)mg * N + ng] = v;
                }
            }
        }
    }
}

// ---------------------------------------------------------------------------
// LayerNorm; optionally also writes split-bf16 copy
// ---------------------------------------------------------------------------
template<bool PACK>
__global__ void ln_kernel(const float* __restrict__ x,
                          const float* __restrict__ w,
                          const float* __restrict__ b,
                          float* __restrict__ y,
                          __nv_bfloat16* __restrict__ yh,
                          __nv_bfloat16* __restrict__ yl)
{
    int r = blockIdx.x;
    int t = threadIdx.x;
    const float* xr = x + (size_t)r * DD;

    float v0 = xr[t], v1 = xr[t + 256];
    float s  = v0 + v1;
    float sq = v0 * v0 + v1 * v1;

#pragma unroll
    for (int off = 16; off; off >>= 1) {
        s  += __shfl_xor_sync(0xffffffffu, s,  off);
        sq += __shfl_xor_sync(0xffffffffu, sq, off);
    }
    __shared__ float sw[8], sqw[8];
    if ((t & 31) == 0) { sw[t >> 5] = s; sqw[t >> 5] = sq; }
    __syncthreads();
    s  = sw[0] + sw[1] + sw[2] + sw[3] + sw[4] + sw[5] + sw[6] + sw[7];
    sq = sqw[0] + sqw[1] + sqw[2] + sqw[3] + sqw[4] + sqw[5] + sqw[6] + sqw[7];

    float mean = s * (1.f / DD);
    float var  = sq * (1.f / DD) - mean * mean;
    float inv  = rsqrtf(var + 1e-5f);

    float r0 = (v0 - mean) * inv * w[t]       + b[t];
    float r1 = (v1 - mean) * inv * w[t + 256] + b[t + 256];
    float* yr = y + (size_t)r * DD;
    yr[t]       = r0;
    yr[t + 256] = r1;
    if (PACK) {
        size_t base = (size_t)r * DD;
        __nv_bfloat16 h0 = __float2bfloat16(r0);
        __nv_bfloat16 h1 = __float2bfloat16(r1);
        yh[base + t]       = h0;
        yh[base + t + 256] = h1;
        yl[base + t]       = __float2bfloat16(r0 - __bfloat162float(h0));
        yl[base + t + 256] = __float2bfloat16(r1 - __bfloat162float(h1));
    }
}

// ---------------------------------------------------------------------------
// Host launcher
// ---------------------------------------------------------------------------
extern "C" void kernel_launch(void* const* d_in, const int* in_sizes, int n_in,
                              void* d_out, int out_size)
{
    const int*   x    = (const int*)  d_in[0];
    const float* emb  = (const float*)d_in[1];
    const float* pe   = (const float*)d_in[2];
    const float* Wq   = (const float*)d_in[3];
    const float* Wk   = (const float*)d_in[4];
    const float* Wv   = (const float*)d_in[5];
    const float* Wo   = (const float*)d_in[6];
    const float* bo   = (const float*)d_in[7];
    const float* ln1w = (const float*)d_in[8];
    const float* ln1b = (const float*)d_in[9];
    const float* W1   = (const float*)d_in[10];
    const float* b1   = (const float*)d_in[11];
    const float* W2   = (const float*)d_in[12];
    const float* b2   = (const float*)d_in[13];
    const float* ln2w = (const float*)d_in[14];
    const float* ln2b = (const float*)d_in[15];
    float* out = (float*)d_out;

    float *h, *q, *k, *v, *t, *n1;
    __nv_bfloat16 *oh, *ol, *n1h, *n1l, *ffh, *ffl;
    __nv_bfloat16 *woh, *wol, *w1h, *w1l, *w2h, *w2l;
    cudaGetSymbolAddress((void**)&h,   g_h);
    cudaGetSymbolAddress((void**)&q,   g_q);
    cudaGetSymbolAddress((void**)&k,   g_k);
    cudaGetSymbolAddress((void**)&v,   g_v);
    cudaGetSymbolAddress((void**)&t,   g_t);
    cudaGetSymbolAddress((void**)&n1,  g_n1);
    cudaGetSymbolAddress((void**)&oh,  g_oh);
    cudaGetSymbolAddress((void**)&ol,  g_ol);
    cudaGetSymbolAddress((void**)&n1h, g_n1h);
    cudaGetSymbolAddress((void**)&n1l, g_n1l);
    cudaGetSymbolAddress((void**)&ffh, g_ffh);
    cudaGetSymbolAddress((void**)&ffl, g_ffl);
    cudaGetSymbolAddress((void**)&woh, g_woh);
    cudaGetSymbolAddress((void**)&wol, g_wol);
    cudaGetSymbolAddress((void**)&w1h, g_w1h);
    cudaGetSymbolAddress((void**)&w1l, g_w1l);
    cudaGetSymbolAddress((void**)&w2h, g_w2h);
    cudaGetSymbolAddress((void**)&w2l, g_w2l);

    cudaFuncSetAttribute(gemm_mma_kernel<false, true,  false>,
                         cudaFuncAttributeMaxDynamicSharedMemorySize, G_SMEM);
    cudaFuncSetAttribute(gemm_mma_kernel<true,  false, true>,
                         cudaFuncAttributeMaxDynamicSharedMemorySize, G_SMEM);

    // split-pack weights (cheap, deterministic, graph-capturable)
    pack2_kernel<<<(LL*DD*DD + 255) / 256, 256>>>(Wo, woh, wol, LL*DD*DD);
    pack2_kernel<<<(LL*FF*DD + 255) / 256, 256>>>(W1, w1h, w1l, LL*FF*DD);
    pack2_kernel<<<(LL*DD*FF + 255) / 256, 256>>>(W2, w2h, w2l, LL*DD*FF);

    embed_kernel<<<MM * DD / 256, 256>>>(x, emb, pe, h);

    for (int l = 0; l < LL; l++) {
        qkv2_kernel<<<dim3(BB * HH, NQT, 2), 256>>>(
            h, Wq + l * HD * HD, Wk + l * HD * HD, Wv + l * HD * HD, q, k, v);

        attn2_kernel<<<dim3(BB * HH, NQT), 256>>>(q, k, v, oh, ol);

        // t = o @ Wo^T + bo + h   (fp32 out)
        gemm_mma_kernel<false, true, false><<<dim3(DD / 128, MM / 128), 256, G_SMEM>>>(
            oh, ol, woh + (size_t)l * DD * DD, wol + (size_t)l * DD * DD,
            bo + l * DD, h, t, nullptr, nullptr, MM, DD, DD);

        ln_kernel<true><<<MM, 256>>>(t, ln1w + l * DD, ln1b + l * DD, n1, n1h, n1l);

        // ff = relu(n1 @ W1^T + b1)  (split-bf16 out)
        gemm_mma_kernel<true, false, true><<<dim3(FF / 128, MM / 128), 256, G_SMEM>>>(
            n1h, n1l, w1h + (size_t)l * FF * DD, w1l + (size_t)l * FF * DD,
            b1 + l * FF, nullptr, nullptr, ffh, ffl, MM, FF, DD);

        // t = ff @ W2^T + b2 + n1  (fp32 out)
        gemm_mma_kernel<false, true, false><<<dim3(DD / 128, MM / 128), 256, G_SMEM>>>(
            ffh, ffl, w2h + (size_t)l * DD * FF, w2l + (size_t)l * DD * FF,
            b2 + l * DD, n1, t, nullptr, nullptr, MM, DD, FF);

        float* dst = (l == LL - 1) ? out : h;
        ln_kernel<false><<<MM, 256>>>(t, ln2w + l * DD, ln2b + l * DD, dst, nullptr, nullptr);
    }
}

// round 12
// speedup vs baseline: 6.9575x; 1.2800x over previous
#include <cuda_runtime.h>
#include <cuda_bf16.h>
#include <math.h>
#include <stdint.h>

// Problem constants
#define BB 32
#define SS 744
#define SP 768          // padded sequence for mma attention
#define DD 512
#define HH 8
#define HD 64
#define LL 4
#define MM (BB*SS)      // 23808 = 128*186
#define FF (4*DD)       // 2048

__device__ __forceinline__ uint32_t smem_u32(const void* p) {
    uint32_t a;
    asm("{ .reg .u64 t; cvta.to.shared.u64 t, %1; cvt.u32.u64 %0, t; }" : "=r"(a) : "l"(p));
    return a;
}
__device__ __forceinline__ void cp16(uint32_t dst, const void* src) {
    asm volatile("cp.async.cg.shared.global [%0], [%1], 16;" :: "r"(dst), "l"(src) : "memory");
}
#define CP_COMMIT() asm volatile("cp.async.commit_group;" ::: "memory")
#define CP_WAIT1()  asm volatile("cp.async.wait_group 1;" ::: "memory")
#define CP_WAIT0()  asm volatile("cp.async.wait_group 0;" ::: "memory")

// pack two f32 -> bf16x2 (lo in bits 0-15, hi in bits 16-31)
__device__ __forceinline__ uint32_t pk2(float lo, float hi) {
    uint32_t r;
    asm("cvt.rn.bf16x2.f32 %0, %1, %2;" : "=r"(r) : "f"(hi), "f"(lo));
    return r;
}

#define MMA_BF16(c, a, b) \
    asm volatile("mma.sync.aligned.m16n8k16.row.col.f32.bf16.bf16.f32 " \
        "{%0,%1,%2,%3}, {%4,%5,%6,%7}, {%8,%9}, {%0,%1,%2,%3};" \
        : "+f"((c)[0]), "+f"((c)[1]), "+f"((c)[2]), "+f"((c)[3]) \
        : "r"((a)[0]), "r"((a)[1]), "r"((a)[2]), "r"((a)[3]), \
          "r"((b)[0]), "r"((b)[1]))

#define LDMATRIX_X4(r, addr) \
    asm volatile("ldmatrix.sync.aligned.m8n8.x4.shared.b16 {%0,%1,%2,%3}, [%4];" \
        : "=r"((r)[0]), "=r"((r)[1]), "=r"((r)[2]), "=r"((r)[3]) : "r"(addr))

#define LDMATRIX_X4T(r, addr) \
    asm volatile("ldmatrix.sync.aligned.m8n8.x4.trans.shared.b16 {%0,%1,%2,%3}, [%4];" \
        : "=r"((r)[0]), "=r"((r)[1]), "=r"((r)[2]), "=r"((r)[3]) : "r"(addr))

#define LDMATRIX_X2(r, addr) \
    asm volatile("ldmatrix.sync.aligned.m8n8.x2.shared.b16 {%0,%1}, [%2];" \
        : "=r"((r)[0]), "=r"((r)[1]) : "r"(addr))

// ---------------------------------------------------------------------------
// Scratch (device globals)
// ---------------------------------------------------------------------------
__device__ float g_h [MM*DD];
__device__ float g_t [MM*DD];
__device__ float g_n1[MM*DD];
// bf16 attention operands, padded to SP rows, layout [B*H, SP, HD]
__device__ __nv_bfloat16 g_qh[(size_t)BB*HH*SP*HD];   // pre-scaled by 0.125
__device__ __nv_bfloat16 g_kh[(size_t)BB*HH*SP*HD];
__device__ __nv_bfloat16 g_vh[(size_t)BB*HH*SP*HD];
__device__ __nv_bfloat16 g_vl[(size_t)BB*HH*SP*HD];
// split-bf16 activations (hi, lo)
__device__ __nv_bfloat16 g_oh [MM*DD];
__device__ __nv_bfloat16 g_ol [MM*DD];
__device__ __nv_bfloat16 g_n1h[MM*DD];
__device__ __nv_bfloat16 g_n1l[MM*DD];
__device__ __nv_bfloat16 g_ffh[(size_t)MM*FF];
__device__ __nv_bfloat16 g_ffl[(size_t)MM*FF];
// split-bf16 weights
__device__ __nv_bfloat16 g_woh[LL*DD*DD];
__device__ __nv_bfloat16 g_wol[LL*DD*DD];
__device__ __nv_bfloat16 g_w1h[LL*FF*DD];
__device__ __nv_bfloat16 g_w1l[LL*FF*DD];
__device__ __nv_bfloat16 g_w2h[(size_t)LL*DD*FF];
__device__ __nv_bfloat16 g_w2l[(size_t)LL*DD*FF];

// ---------------------------------------------------------------------------
// fp32 -> split-bf16 (hi + lo)
// ---------------------------------------------------------------------------
__global__ void pack2_kernel(const float* __restrict__ in,
                             __nv_bfloat16* __restrict__ hi,
                             __nv_bfloat16* __restrict__ lo, int n)
{
    int i = blockIdx.x * 256 + threadIdx.x;
    if (i < n) {
        float v = in[i];
        __nv_bfloat16 hb = __float2bfloat16(v);
        hi[i] = hb;
        lo[i] = __float2bfloat16(v - __bfloat162float(hb));
    }
}

// ---------------------------------------------------------------------------
// Embedding
// ---------------------------------------------------------------------------
__global__ void embed_kernel(const int* __restrict__ x,
                             const float* __restrict__ emb,
                             const float* __restrict__ pe,
                             float* __restrict__ h)
{
    int idx = blockIdx.x * 256 + threadIdx.x;
    int d   = idx & (DD - 1);
    int ms  = idx >> 9;
    int s   = ms % SS;
    int tok = x[ms];
    h[idx] = emb[tok * DD + d] * 22.627416997969522f + pe[s * DD + d];
}

// ---------------------------------------------------------------------------
// QKV: smem micro-GEMM (fp32 math), bf16 outputs, padded to SP rows.
// grid = (B*H, SP/32, 2); block = 256.
// ---------------------------------------------------------------------------
__global__ __launch_bounds__(256) void qkv2_kernel(
        const float* __restrict__ h,
        const float* __restrict__ Wq,
        const float* __restrict__ Wk,
        const float* __restrict__ Wv,
        __nv_bfloat16* __restrict__ qh,
        __nv_bfloat16* __restrict__ kh,
        __nv_bfloat16* __restrict__ vh,
        __nv_bfloat16* __restrict__ vl)
{
    __shared__ float Ws3[3][HD][33];
    __shared__ float Xs[32][HD];

    const int bh  = blockIdx.x;
    const int b   = bh >> 3;
    const int hh  = bh & 7;
    const int s0  = blockIdx.y * 32;
    const int e0  = blockIdx.z * 32;
    const int tid = threadIdx.x;

#pragma unroll
    for (int i = 0; i < 6; i++) {
        int idx = tid + i * 256;
        int m   = idx >> 9;
        int r   = idx & 511;
        int el  = r >> 4;
        int d4  = (r & 15) * 4;
        const float* Wm = (m == 0) ? Wq : (m == 1) ? Wk : Wv;
        float4 a = *(const float4*)(Wm + (e0 + el) * HD + d4);
        Ws3[m][d4 + 0][el] = a.x;
        Ws3[m][d4 + 1][el] = a.y;
        Ws3[m][d4 + 2][el] = a.z;
        Ws3[m][d4 + 3][el] = a.w;
    }
#pragma unroll
    for (int i = 0; i < 2; i++) {
        int f   = tid + i * 256;
        int row = f >> 4;
        int c4  = f & 15;
        int sg  = s0 + row; if (sg > SS - 1) sg = SS - 1;
        ((float4*)Xs[row])[c4] =
            *(const float4*)(h + (size_t)(b * SS + sg) * DD + hh * HD + c4 * 4);
    }
    __syncthreads();

    const int el = tid & 31;
    const int ty = tid >> 5;

    float aq[4] = {}, ak[4] = {}, av[4] = {};
#pragma unroll
    for (int d = 0; d < HD; d++) {
        float wq = Ws3[0][d][el];
        float wk = Ws3[1][d][el];
        float wv = Ws3[2][d][el];
#pragma unroll
        for (int r = 0; r < 4; r++) {
            float xv = Xs[ty * 4 + r][d];
            aq[r] += xv * wq;
            ak[r] += xv * wk;
            av[r] += xv * wv;
        }
    }
#pragma unroll
    for (int r = 0; r < 4; r++) {
        int s = s0 + ty * 4 + r;
        size_t oi = ((size_t)bh * SP + s) * HD + e0 + el;
        if (s < SS) {
            qh[oi] = __float2bfloat16(aq[r] * 0.125f);   // fold 1/sqrt(64)
            kh[oi] = __float2bfloat16(ak[r]);
            __nv_bfloat16 hb = __float2bfloat16(av[r]);
            vh[oi] = hb;
            vl[oi] = __float2bfloat16(av[r] - __bfloat162float(hb));
        } else {
            qh[oi] = __float2bfloat16(0.f);
            kh[oi] = __float2bfloat16(0.f);
            vh[oi] = __float2bfloat16(0.f);
            vl[oi] = __float2bfloat16(0.f);
        }
    }
}

// ---------------------------------------------------------------------------
// Attention v3: FA2-style mma.sync flash attention.
// grid = (B*H, SP/64); block = 128 (4 warps, 16 query rows each).
// Keys in 64-wide cp.async double-buffered tiles.
// Scores: single bf16 product. PV: split-bf16 P x split-bf16 V (3 products).
// smem: Qs[64][72] + 2 stages x (K|Vh|Vl each [64][72]) = 64512 B dynamic.
// ---------------------------------------------------------------------------
#define AT_ROW   144          // bytes per smem row (72 halves)
#define AT_MAT   9216         // one 64x72 matrix
#define AT_STAGE 27648        // K+Vh+Vl
#define AT_SMEM  (AT_MAT + 2*AT_STAGE)   // 64512

__global__ __launch_bounds__(128) void attn3_kernel(
        const __nv_bfloat16* __restrict__ Qh,
        const __nv_bfloat16* __restrict__ Kh,
        const __nv_bfloat16* __restrict__ Vh,
        const __nv_bfloat16* __restrict__ Vl,
        __nv_bfloat16* __restrict__ Oh,
        __nv_bfloat16* __restrict__ Ol)
{
    extern __shared__ char asmem[];
    const uint32_t sb   = smem_u32(asmem);
    const int bh   = blockIdx.x;
    const int qt   = blockIdx.y;
    const int tid  = threadIdx.x;
    const int lane = tid & 31;
    const int w    = tid >> 5;

    const size_t gbase = (size_t)bh * SP * HD;

    const int srow = tid >> 3;            // 0..15 (+16 per it)
    const int sc8  = (tid & 7) * 8;       // half offset in 64-wide row

    // ---- stage Q tile + KV tile 0 (one cp.async group) ----
#pragma unroll
    for (int it = 0; it < 4; it++) {
        int r = srow + it * 16;
        cp16(sb + r * AT_ROW + sc8 * 2,
             Qh + gbase + (size_t)(qt * 64 + r) * HD + sc8);
    }
    {
        const uint32_t base = sb + AT_MAT;       // stage 0
#pragma unroll
        for (int it = 0; it < 4; it++) {
            int r = srow + it * 16;
            size_t gi = gbase + (size_t)r * HD + sc8;
            uint32_t d = base + r * AT_ROW + sc8 * 2;
            cp16(d,              Kh + gi);
            cp16(d + AT_MAT,     Vh + gi);
            cp16(d + 2*AT_MAT,   Vl + gi);
        }
    }
    CP_COMMIT();

    // frag addressing constants
    const int l16   = lane & 15;
    const int arow  = l16;                       // A-frag rows 0..15
    const int acsel = (lane >> 4) * 8;           // A-frag col half-select
    const int kbrow = l16 & 7;                   // K B-frag row
    const int kbsel = (l16 >> 3) * 8;            // K B-frag col half
    const int vrow  = l16;                       // V trans rows
    const int vcsel = (lane & 16) ? 8 : 0;       // V trans col half

    uint32_t qf[4][4];
    float of[8][4] = {};
    float m_lo = -1e30f, m_hi = -1e30f, l_lo = 0.f, l_hi = 0.f;

    CP_WAIT0();
    __syncthreads();

    // Q fragments (persist in registers)
#pragma unroll
    for (int kk = 0; kk < 4; kk++) {
        uint32_t a = sb + (w * 16 + arow) * AT_ROW + (kk * 16 + acsel) * 2;
        LDMATRIX_X4(qf[kk], a);
    }

    for (int kt = 0; kt < SP / 64; kt++) {
        if (kt > 0) { CP_WAIT0(); __syncthreads(); }
        if (kt + 1 < SP / 64) {
            const uint32_t base = sb + AT_MAT + ((kt + 1) & 1) * AT_STAGE;
            const size_t   gr   = gbase + (size_t)((kt + 1) * 64) * HD;
#pragma unroll
            for (int it = 0; it < 4; it++) {
                int r = srow + it * 16;
                size_t gi = gr + (size_t)r * HD + sc8;
                uint32_t d = base + r * AT_ROW + sc8 * 2;
                cp16(d,            Kh + gi);
                cp16(d + AT_MAT,   Vh + gi);
                cp16(d + 2*AT_MAT, Vl + gi);
            }
            CP_COMMIT();
        }
        const uint32_t kb = sb + AT_MAT + (kt & 1) * AT_STAGE;

        // ---- scores S = Q K^T (single bf16 product) ----
        float sf[8][4];
#pragma unroll
        for (int nt = 0; nt < 8; nt++)
            sf[nt][0] = sf[nt][1] = sf[nt][2] = sf[nt][3] = 0.f;
#pragma unroll
        for (int kk = 0; kk < 4; kk++) {
#pragma unroll
            for (int nt = 0; nt < 8; nt++) {
                uint32_t bfr[2];
                LDMATRIX_X2(bfr, kb + (nt * 8 + kbrow) * AT_ROW + (kk * 16 + kbsel) * 2);
                MMA_BF16(sf[nt], qf[kk], bfr);
            }
        }
        if (kt == SP / 64 - 1) {    // keys 744..767 invalid: nt 5..7 exactly
#pragma unroll
            for (int nt = 5; nt < 8; nt++)
                sf[nt][0] = sf[nt][1] = sf[nt][2] = sf[nt][3] = -1e30f;
        }

        // ---- online softmax on fragments ----
        float ml = -1e30f, mh = -1e30f;
#pragma unroll
        for (int nt = 0; nt < 8; nt++) {
            ml = fmaxf(ml, fmaxf(sf[nt][0], sf[nt][1]));
            mh = fmaxf(mh, fmaxf(sf[nt][2], sf[nt][3]));
        }
        ml = fmaxf(ml, __shfl_xor_sync(0xffffffffu, ml, 1));
        ml = fmaxf(ml, __shfl_xor_sync(0xffffffffu, ml, 2));
        mh = fmaxf(mh, __shfl_xor_sync(0xffffffffu, mh, 1));
        mh = fmaxf(mh, __shfl_xor_sync(0xffffffffu, mh, 2));

        float nml = fmaxf(m_lo, ml), nmh = fmaxf(m_hi, mh);
        float cl = __expf(m_lo - nml), ch = __expf(m_hi - nmh);
        m_lo = nml; m_hi = nmh;
        l_lo *= cl; l_hi *= ch;

#pragma unroll
        for (int nt = 0; nt < 8; nt++) {
            float p0 = __expf(sf[nt][0] - nml);
            float p1 = __expf(sf[nt][1] - nml);
            float p2 = __expf(sf[nt][2] - nmh);
            float p3 = __expf(sf[nt][3] - nmh);
            l_lo += p0 + p1;  l_hi += p2 + p3;
            sf[nt][0] = p0; sf[nt][1] = p1; sf[nt][2] = p2; sf[nt][3] = p3;
        }
#pragma unroll
        for (int dt = 0; dt < 8; dt++) {
            of[dt][0] *= cl; of[dt][1] *= cl;
            of[dt][2] *= ch; of[dt][3] *= ch;
        }

        // ---- O += P V (split-bf16 P, split-bf16 V: 3 products) ----
        const uint32_t vbh = kb + AT_MAT;
        const uint32_t vbl = kb + 2 * AT_MAT;
#pragma unroll
        for (int kc = 0; kc < 4; kc++) {
            const float* pA = sf[2 * kc];
            const float* pB = sf[2 * kc + 1];
            // hi fragments
            uint32_t ah[4], al[4];
            ah[0] = pk2(pA[0], pA[1]);
            ah[1] = pk2(pA[2], pA[3]);
            ah[2] = pk2(pB[0], pB[1]);
            ah[3] = pk2(pB[2], pB[3]);
            // lo fragments (residuals)
            {
                float rA0 = pA[0] - __bfloat162float(__float2bfloat16(pA[0]));
                float rA1 = pA[1] - __bfloat162float(__float2bfloat16(pA[1]));
                float rA2 = pA[2] - __bfloat162float(__float2bfloat16(pA[2]));
                float rA3 = pA[3] - __bfloat162float(__float2bfloat16(pA[3]));
                float rB0 = pB[0] - __bfloat162float(__float2bfloat16(pB[0]));
                float rB1 = pB[1] - __bfloat162float(__float2bfloat16(pB[1]));
                float rB2 = pB[2] - __bfloat162float(__float2bfloat16(pB[2]));
                float rB3 = pB[3] - __bfloat162float(__float2bfloat16(pB[3]));
                al[0] = pk2(rA0, rA1);
                al[1] = pk2(rA2, rA3);
                al[2] = pk2(rB0, rB1);
                al[3] = pk2(rB2, rB3);
            }
#pragma unroll
            for (int dtp = 0; dtp < 4; dtp++) {
                uint32_t vh4[4], vl4[4];
                uint32_t vaddr = (kc * 16 + vrow) * AT_ROW + (dtp * 16 + vcsel) * 2;
                LDMATRIX_X4T(vh4, vbh + vaddr);
                LDMATRIX_X4T(vl4, vbl + vaddr);
                uint32_t bh0[2] = { vh4[0], vh4[1] };
                uint32_t bh1[2] = { vh4[2], vh4[3] };
                uint32_t bl0[2] = { vl4[0], vl4[1] };
                uint32_t bl1[2] = { vl4[2], vl4[3] };
                MMA_BF16(of[2 * dtp],     ah, bh0);
                MMA_BF16(of[2 * dtp],     ah, bl0);
                MMA_BF16(of[2 * dtp],     al, bh0);
                MMA_BF16(of[2 * dtp + 1], ah, bh1);
                MMA_BF16(of[2 * dtp + 1], ah, bl1);
                MMA_BF16(of[2 * dtp + 1], al, bh1);
            }
        }
    }

    // ---- epilogue: normalize, split-bf16, write [B,S,D] ----
    l_lo += __shfl_xor_sync(0xffffffffu, l_lo, 1);
    l_lo += __shfl_xor_sync(0xffffffffu, l_lo, 2);
    l_hi += __shfl_xor_sync(0xffffffffu, l_hi, 1);
    l_hi += __shfl_xor_sync(0xffffffffu, l_hi, 2);
    float il = 1.f / l_lo, ih = 1.f / l_hi;

    const int b    = bh >> 3;
    const int hh2  = bh & 7;
    const int s_lo = qt * 64 + w * 16 + (lane >> 2);
    const int s_hi = s_lo + 8;
    const int dcol = hh2 * HD + 2 * (lane & 3);

#pragma unroll
    for (int dt = 0; dt < 8; dt++) {
        int d = dcol + dt * 8;
        if (s_lo < SS) {
            float v0 = of[dt][0] * il, v1 = of[dt][1] * il;
            float h0 = __bfloat162float(__float2bfloat16(v0));
            float h1 = __bfloat162float(__float2bfloat16(v1));
            size_t idx = (size_t)(b * SS + s_lo) * DD + d;
            *(uint32_t*)(Oh + idx) = pk2(v0, v1);
            *(uint32_t*)(Ol + idx) = pk2(v0 - h0, v1 - h1);
        }
        if (s_hi < SS) {
            float v2 = of[dt][2] * ih, v3 = of[dt][3] * ih;
            float h2 = __bfloat162float(__float2bfloat16(v2));
            float h3 = __bfloat162float(__float2bfloat16(v3));
            size_t idx = (size_t)(b * SS + s_hi) * DD + d;
            *(uint32_t*)(Oh + idx) = pk2(v2, v3);
            *(uint32_t*)(Ol + idx) = pk2(v2 - h2, v3 - h3);
        }
    }
}

// ---------------------------------------------------------------------------
// Tensor-core GEMM via mma.sync, split-bf16, cp.async double-buffered.
// (unchanged from R11 — MMA-throughput-bound at legacy-HMMA rate)
// ---------------------------------------------------------------------------
#define G_ROWB   80
#define G_MAT    10240
#define G_STAGE  40960
#define G_SMEM   81920

template<bool RELU, bool RESID, bool PACKOUT>
__global__ __launch_bounds__(256, 2) void gemm_mma_kernel(
        const __nv_bfloat16* __restrict__ Ah, const __nv_bfloat16* __restrict__ Al,
        const __nv_bfloat16* __restrict__ Wh, const __nv_bfloat16* __restrict__ Wl,
        const float* __restrict__ bias, const float* __restrict__ R,
        float* __restrict__ Cf,
        __nv_bfloat16* __restrict__ Ch, __nv_bfloat16* __restrict__ Cl,
        int M, int N, int K)
{
    extern __shared__ char dsm[];
    const uint32_t sb = smem_u32(dsm);

    const int tid  = threadIdx.x;
    const int lane = tid & 31;
    const int wid  = tid >> 5;
    const int wm   = (wid & 1) * 64;
    const int wn   = (wid >> 1) * 32;
    const int m0   = blockIdx.y * 128;
    const int n0   = blockIdx.x * 128;

    float acc[4][4][4] = {};

    const int prow0 = tid >> 2;
    const int prow1 = prow0 + 64;
    const int pc8   = (tid & 3) * 8;
    const uint32_t pdst0 = (uint32_t)(prow0 * G_ROWB + pc8 * 2);
    const uint32_t pdst1 = (uint32_t)(prow1 * G_ROWB + pc8 * 2);

    const int arow  = lane & 15;
    const int acsel = (lane >> 4) * 8;
    const int l16   = lane & 15;
    const int brow  = l16 & 7;
    const int bcsel = (l16 >> 3) * 8;

    const int nchunk = K >> 5;

    auto prefetch = [&](int kc, int st) {
        const int k0 = kc << 5;
        const uint32_t s0 = sb + st * G_STAGE;
        cp16(s0 + 0*G_MAT + pdst0, Ah + (size_t)(m0 + prow0) * K + k0 + pc8);
        cp16(s0 + 0*G_MAT + pdst1, Ah + (size_t)(m0 + prow1) * K + k0 + pc8);
        cp16(s0 + 1*G_MAT + pdst0, Al + (size_t)(m0 + prow0) * K + k0 + pc8);
        cp16(s0 + 1*G_MAT + pdst1, Al + (size_t)(m0 + prow1) * K + k0 + pc8);
        cp16(s0 + 2*G_MAT + pdst0, Wh + (size_t)(n0 + prow0) * K + k0 + pc8);
        cp16(s0 + 2*G_MAT + pdst1, Wh + (size_t)(n0 + prow1) * K + k0 + pc8);
        cp16(s0 + 3*G_MAT + pdst0, Wl + (size_t)(n0 + prow0) * K + k0 + pc8);
        cp16(s0 + 3*G_MAT + pdst1, Wl + (size_t)(n0 + prow1) * K + k0 + pc8);
    };

    prefetch(0, 0);
    CP_COMMIT();

    for (int kc = 0; kc < nchunk; kc++) {
        const int st = kc & 1;
        if (kc + 1 < nchunk) {
            prefetch(kc + 1, st ^ 1);
            CP_COMMIT();
            CP_WAIT1();
        } else {
            CP_WAIT0();
        }
        __syncthreads();

        const uint32_t s0 = sb + st * G_STAGE;
#pragma unroll
        for (int ks = 0; ks < 2; ks++) {
            const int kcol = ks * 16;

            uint32_t bh[4][2], bl[4][2];
#pragma unroll
            for (int nt = 0; nt < 4; nt++) {
                uint32_t r = (uint32_t)((wn + nt * 8 + brow) * G_ROWB + (kcol + bcsel) * 2);
                LDMATRIX_X2(bh[nt], s0 + 2*G_MAT + r);
                LDMATRIX_X2(bl[nt], s0 + 3*G_MAT + r);
            }
#pragma unroll
            for (int mt = 0; mt < 4; mt++) {
                uint32_t ahf[4], alf[4];
                uint32_t r = (uint32_t)((wm + mt * 16 + arow) * G_ROWB + (kcol + acsel) * 2);
                LDMATRIX_X4(ahf, s0 + 0*G_MAT + r);
                LDMATRIX_X4(alf, s0 + 1*G_MAT + r);
#pragma unroll
                for (int nt = 0; nt < 4; nt++) {
                    MMA_BF16(acc[mt][nt], ahf, bh[nt]);
                    MMA_BF16(acc[mt][nt], ahf, bl[nt]);
                    MMA_BF16(acc[mt][nt], alf, bh[nt]);
                }
            }
        }
        __syncthreads();
    }

    const int r4 = lane >> 2;
    const int c2 = (lane & 3) * 2;
#pragma unroll
    for (int mt = 0; mt < 4; mt++) {
#pragma unroll
        for (int nt = 0; nt < 4; nt++) {
#pragma unroll
            for (int e = 0; e < 4; e++) {
                int mg = m0 + wm + mt * 16 + r4 + (e >> 1) * 8;
                int ng = n0 + wn + nt * 8 + c2 + (e & 1);
                float v = acc[mt][nt][e] + bias[ng];
                if (RELU)  v = fmaxf(v, 0.f);
                if (RESID) v += R[(size_t)mg * N + ng];
                if (PACKOUT) {
                    __nv_bfloat16 hb = __float2bfloat16(v);
                    Ch[(size_t)mg * N + ng] = hb;
                    Cl[(size_t)mg * N + ng] = __float2bfloat16(v - __bfloat162float(hb));
                } else {
                    Cf[(size_t)mg * N + ng] = v;
                }
            }
        }
    }
}

// ---------------------------------------------------------------------------
// LayerNorm; optionally also writes split-bf16 copy
// ---------------------------------------------------------------------------
template<bool PACK>
__global__ void ln_kernel(const float* __restrict__ x,
                          const float* __restrict__ w,
                          const float* __restrict__ b,
                          float* __restrict__ y,
                          __nv_bfloat16* __restrict__ yh,
                          __nv_bfloat16* __restrict__ yl)
{
    int r = blockIdx.x;
    int t = threadIdx.x;
    const float* xr = x + (size_t)r * DD;

    float v0 = xr[t], v1 = xr[t + 256];
    float s  = v0 + v1;
    float sq = v0 * v0 + v1 * v1;

#pragma unroll
    for (int off = 16; off; off >>= 1) {
        s  += __shfl_xor_sync(0xffffffffu, s,  off);
        sq += __shfl_xor_sync(0xffffffffu, sq, off);
    }
    __shared__ float sw[8], sqw[8];
    if ((t & 31) == 0) { sw[t >> 5] = s; sqw[t >> 5] = sq; }
    __syncthreads();
    s  = sw[0] + sw[1] + sw[2] + sw[3] + sw[4] + sw[5] + sw[6] + sw[7];
    sq = sqw[0] + sqw[1] + sqw[2] + sqw[3] + sqw[4] + sqw[5] + sqw[6] + sqw[7];

    float mean = s * (1.f / DD);
    float var  = sq * (1.f / DD) - mean * mean;
    float inv  = rsqrtf(var + 1e-5f);

    float r0 = (v0 - mean) * inv * w[t]       + b[t];
    float r1 = (v1 - mean) * inv * w[t + 256] + b[t + 256];
    float* yr = y + (size_t)r * DD;
    yr[t]       = r0;
    yr[t + 256] = r1;
    if (PACK) {
        size_t base = (size_t)r * DD;
        __nv_bfloat16 h0 = __float2bfloat16(r0);
        __nv_bfloat16 h1 = __float2bfloat16(r1);
        yh[base + t]       = h0;
        yh[base + t + 256] = h1;
        yl[base + t]       = __float2bfloat16(r0 - __bfloat162float(h0));
        yl[base + t + 256] = __float2bfloat16(r1 - __bfloat162float(h1));
    }
}

// ---------------------------------------------------------------------------
// Host launcher
// ---------------------------------------------------------------------------
extern "C" void kernel_launch(void* const* d_in, const int* in_sizes, int n_in,
                              void* d_out, int out_size)
{
    const int*   x    = (const int*)  d_in[0];
    const float* emb  = (const float*)d_in[1];
    const float* pe   = (const float*)d_in[2];
    const float* Wq   = (const float*)d_in[3];
    const float* Wk   = (const float*)d_in[4];
    const float* Wv   = (const float*)d_in[5];
    const float* Wo   = (const float*)d_in[6];
    const float* bo   = (const float*)d_in[7];
    const float* ln1w = (const float*)d_in[8];
    const float* ln1b = (const float*)d_in[9];
    const float* W1   = (const float*)d_in[10];
    const float* b1   = (const float*)d_in[11];
    const float* W2   = (const float*)d_in[12];
    const float* b2   = (const float*)d_in[13];
    const float* ln2w = (const float*)d_in[14];
    const float* ln2b = (const float*)d_in[15];
    float* out = (float*)d_out;

    float *h, *t, *n1;
    __nv_bfloat16 *qh, *kh, *vh, *vl;
    __nv_bfloat16 *oh, *ol, *n1h, *n1l, *ffh, *ffl;
    __nv_bfloat16 *woh, *wol, *w1h, *w1l, *w2h, *w2l;
    cudaGetSymbolAddress((void**)&h,   g_h);
    cudaGetSymbolAddress((void**)&t,   g_t);
    cudaGetSymbolAddress((void**)&n1,  g_n1);
    cudaGetSymbolAddress((void**)&qh,  g_qh);
    cudaGetSymbolAddress((void**)&kh,  g_kh);
    cudaGetSymbolAddress((void**)&vh,  g_vh);
    cudaGetSymbolAddress((void**)&vl,  g_vl);
    cudaGetSymbolAddress((void**)&oh,  g_oh);
    cudaGetSymbolAddress((void**)&ol,  g_ol);
    cudaGetSymbolAddress((void**)&n1h, g_n1h);
    cudaGetSymbolAddress((void**)&n1l, g_n1l);
    cudaGetSymbolAddress((void**)&ffh, g_ffh);
    cudaGetSymbolAddress((void**)&ffl, g_ffl);
    cudaGetSymbolAddress((void**)&woh, g_woh);
    cudaGetSymbolAddress((void**)&wol, g_wol);
    cudaGetSymbolAddress((void**)&w1h, g_w1h);
    cudaGetSymbolAddress((void**)&w1l, g_w1l);
    cudaGetSymbolAddress((void**)&w2h, g_w2h);
    cudaGetSymbolAddress((void**)&w2l, g_w2l);

    cudaFuncSetAttribute(gemm_mma_kernel<false, true,  false>,
                         cudaFuncAttributeMaxDynamicSharedMemorySize, G_SMEM);
    cudaFuncSetAttribute(gemm_mma_kernel<true,  false, true>,
                         cudaFuncAttributeMaxDynamicSharedMemorySize, G_SMEM);
    cudaFuncSetAttribute(attn3_kernel,
                         cudaFuncAttributeMaxDynamicSharedMemorySize, AT_SMEM);

    pack2_kernel<<<(LL*DD*DD + 255) / 256, 256>>>(Wo, woh, wol, LL*DD*DD);
    pack2_kernel<<<(LL*FF*DD + 255) / 256, 256>>>(W1, w1h, w1l, LL*FF*DD);
    pack2_kernel<<<(LL*DD*FF + 255) / 256, 256>>>(W2, w2h, w2l, LL*DD*FF);

    embed_kernel<<<MM * DD / 256, 256>>>(x, emb, pe, h);

    for (int l = 0; l < LL; l++) {
        qkv2_kernel<<<dim3(BB * HH, SP / 32, 2), 256>>>(
            h, Wq + l * HD * HD, Wk + l * HD * HD, Wv + l * HD * HD,
            qh, kh, vh, vl);

        attn3_kernel<<<dim3(BB * HH, SP / 64), 128, AT_SMEM>>>(
            qh, kh, vh, vl, oh, ol);

        // t = o @ Wo^T + bo + h   (fp32 out)
        gemm_mma_kernel<false, true, false><<<dim3(DD / 128, MM / 128), 256, G_SMEM>>>(
            oh, ol, woh + (size_t)l * DD * DD, wol + (size_t)l * DD * DD,
            bo + l * DD, h, t, nullptr, nullptr, MM, DD, DD);

        ln_kernel<true><<<MM, 256>>>(t, ln1w + l * DD, ln1b + l * DD, n1, n1h, n1l);

        // ff = relu(n1 @ W1^T + b1)  (split-bf16 out)
        gemm_mma_kernel<true, false, true><<<dim3(FF / 128, MM / 128), 256, G_SMEM>>>(
            n1h, n1l, w1h + (size_t)l * FF * DD, w1l + (size_t)l * FF * DD,
            b1 + l * FF, nullptr, nullptr, ffh, ffl, MM, FF, DD);

        // t = ff @ W2^T + b2 + n1  (fp32 out)
        gemm_mma_kernel<false, true, false><<<dim3(DD / 128, MM / 128), 256, G_SMEM>>>(
            ffh, ffl, w2h + (size_t)l * DD * FF, w2l + (size_t)l * DD * FF,
            b2 + l * DD, n1, t, nullptr, nullptr, MM, DD, FF);

        float* dst = (l == LL - 1) ? out : h;
        ln_kernel<false><<<MM, 256>>>(t, ln2w + l * DD, ln2b + l * DD, dst, nullptr, nullptr);
    }
}

// round 13
// speedup vs baseline: 9.7851x; 1.4064x over previous
#include <cuda_runtime.h>
#include <cuda_bf16.h>
#include <math.h>
#include <stdint.h>

// Problem constants
#define BB 32
#define SS 744
#define SP 768          // padded sequence for mma attention
#define DD 512
#define HH 8
#define HD 64
#define LL 4
#define MM (BB*SS)      // 23808 = 128*186
#define FF (4*DD)       // 2048

__device__ __forceinline__ uint32_t smem_u32(const void* p) {
    uint32_t a;
    asm("{ .reg .u64 t; cvta.to.shared.u64 t, %1; cvt.u32.u64 %0, t; }" : "=r"(a) : "l"(p));
    return a;
}
__device__ __forceinline__ void cp16(uint32_t dst, const void* src) {
    asm volatile("cp.async.cg.shared.global [%0], [%1], 16;" :: "r"(dst), "l"(src) : "memory");
}
#define CP_COMMIT() asm volatile("cp.async.commit_group;" ::: "memory")
#define CP_WAIT1()  asm volatile("cp.async.wait_group 1;" ::: "memory")
#define CP_WAIT0()  asm volatile("cp.async.wait_group 0;" ::: "memory")

// pack two f32 -> bf16x2 (lo in bits 0-15, hi in bits 16-31)
__device__ __forceinline__ uint32_t pk2(float lo, float hi) {
    uint32_t r;
    asm("cvt.rn.bf16x2.f32 %0, %1, %2;" : "=r"(r) : "f"(hi), "f"(lo));
    return r;
}

#define MMA_BF16(c, a, b) \
    asm volatile("mma.sync.aligned.m16n8k16.row.col.f32.bf16.bf16.f32 " \
        "{%0,%1,%2,%3}, {%4,%5,%6,%7}, {%8,%9}, {%0,%1,%2,%3};" \
        : "+f"((c)[0]), "+f"((c)[1]), "+f"((c)[2]), "+f"((c)[3]) \
        : "r"((a)[0]), "r"((a)[1]), "r"((a)[2]), "r"((a)[3]), \
          "r"((b)[0]), "r"((b)[1]))

#define LDMATRIX_X4(r, addr) \
    asm volatile("ldmatrix.sync.aligned.m8n8.x4.shared.b16 {%0,%1,%2,%3}, [%4];" \
        : "=r"((r)[0]), "=r"((r)[1]), "=r"((r)[2]), "=r"((r)[3]) : "r"(addr))

#define LDMATRIX_X4T(r, addr) \
    asm volatile("ldmatrix.sync.aligned.m8n8.x4.trans.shared.b16 {%0,%1,%2,%3}, [%4];" \
        : "=r"((r)[0]), "=r"((r)[1]), "=r"((r)[2]), "=r"((r)[3]) : "r"(addr))

#define LDMATRIX_X2(r, addr) \
    asm volatile("ldmatrix.sync.aligned.m8n8.x2.shared.b16 {%0,%1}, [%2];" \
        : "=r"((r)[0]), "=r"((r)[1]) : "r"(addr))

// ---------------------------------------------------------------------------
// Scratch (device globals)
// ---------------------------------------------------------------------------
__device__ float g_h [MM*DD];
__device__ float g_t [MM*DD];
// bf16 attention operands, padded to SP rows, layout [B*H, SP, HD]
__device__ __nv_bfloat16 g_qh[(size_t)BB*HH*SP*HD];   // pre-scaled by 0.125
__device__ __nv_bfloat16 g_kh[(size_t)BB*HH*SP*HD];
__device__ __nv_bfloat16 g_vh[(size_t)BB*HH*SP*HD];
__device__ __nv_bfloat16 g_vl[(size_t)BB*HH*SP*HD];
// split-bf16 activations (hi, lo)
__device__ __nv_bfloat16 g_oh [MM*DD];
__device__ __nv_bfloat16 g_ol [MM*DD];
__device__ __nv_bfloat16 g_n1h[MM*DD];
__device__ __nv_bfloat16 g_n1l[MM*DD];
__device__ __nv_bfloat16 g_ffh[(size_t)MM*FF];
__device__ __nv_bfloat16 g_ffl[(size_t)MM*FF];
// split-bf16 weights
__device__ __nv_bfloat16 g_woh[LL*DD*DD];
__device__ __nv_bfloat16 g_wol[LL*DD*DD];
__device__ __nv_bfloat16 g_w1h[LL*FF*DD];
__device__ __nv_bfloat16 g_w1l[LL*FF*DD];
__device__ __nv_bfloat16 g_w2h[(size_t)LL*DD*FF];
__device__ __nv_bfloat16 g_w2l[(size_t)LL*DD*FF];

// ---------------------------------------------------------------------------
// fp32 -> split-bf16 (hi + lo)
// ---------------------------------------------------------------------------
__global__ void pack2_kernel(const float* __restrict__ in,
                             __nv_bfloat16* __restrict__ hi,
                             __nv_bfloat16* __restrict__ lo, int n)
{
    int i = blockIdx.x * 256 + threadIdx.x;
    if (i < n) {
        float v = in[i];
        __nv_bfloat16 hb = __float2bfloat16(v);
        hi[i] = hb;
        lo[i] = __float2bfloat16(v - __bfloat162float(hb));
    }
}

// ---------------------------------------------------------------------------
// Embedding
// ---------------------------------------------------------------------------
__global__ void embed_kernel(const int* __restrict__ x,
                             const float* __restrict__ emb,
                             const float* __restrict__ pe,
                             float* __restrict__ h)
{
    int idx = blockIdx.x * 256 + threadIdx.x;
    int d   = idx & (DD - 1);
    int ms  = idx >> 9;
    int s   = ms % SS;
    int tok = x[ms];
    h[idx] = emb[tok * DD + d] * 22.627416997969522f + pe[s * DD + d];
}

// ---------------------------------------------------------------------------
// QKV: smem micro-GEMM (fp32 math), bf16 outputs, padded to SP rows.
// ---------------------------------------------------------------------------
__global__ __launch_bounds__(256) void qkv2_kernel(
        const float* __restrict__ h,
        const float* __restrict__ Wq,
        const float* __restrict__ Wk,
        const float* __restrict__ Wv,
        __nv_bfloat16* __restrict__ qh,
        __nv_bfloat16* __restrict__ kh,
        __nv_bfloat16* __restrict__ vh,
        __nv_bfloat16* __restrict__ vl)
{
    __shared__ float Ws3[3][HD][33];
    __shared__ float Xs[32][HD];

    const int bh  = blockIdx.x;
    const int b   = bh >> 3;
    const int hh  = bh & 7;
    const int s0  = blockIdx.y * 32;
    const int e0  = blockIdx.z * 32;
    const int tid = threadIdx.x;

#pragma unroll
    for (int i = 0; i < 6; i++) {
        int idx = tid + i * 256;
        int m   = idx >> 9;
        int r   = idx & 511;
        int el  = r >> 4;
        int d4  = (r & 15) * 4;
        const float* Wm = (m == 0) ? Wq : (m == 1) ? Wk : Wv;
        float4 a = *(const float4*)(Wm + (e0 + el) * HD + d4);
        Ws3[m][d4 + 0][el] = a.x;
        Ws3[m][d4 + 1][el] = a.y;
        Ws3[m][d4 + 2][el] = a.z;
        Ws3[m][d4 + 3][el] = a.w;
    }
#pragma unroll
    for (int i = 0; i < 2; i++) {
        int f   = tid + i * 256;
        int row = f >> 4;
        int c4  = f & 15;
        int sg  = s0 + row; if (sg > SS - 1) sg = SS - 1;
        ((float4*)Xs[row])[c4] =
            *(const float4*)(h + (size_t)(b * SS + sg) * DD + hh * HD + c4 * 4);
    }
    __syncthreads();

    const int el = tid & 31;
    const int ty = tid >> 5;

    float aq[4] = {}, ak[4] = {}, av[4] = {};
#pragma unroll
    for (int d = 0; d < HD; d++) {
        float wq = Ws3[0][d][el];
        float wk = Ws3[1][d][el];
        float wv = Ws3[2][d][el];
#pragma unroll
        for (int r = 0; r < 4; r++) {
            float xv = Xs[ty * 4 + r][d];
            aq[r] += xv * wq;
            ak[r] += xv * wk;
            av[r] += xv * wv;
        }
    }
#pragma unroll
    for (int r = 0; r < 4; r++) {
        int s = s0 + ty * 4 + r;
        size_t oi = ((size_t)bh * SP + s) * HD + e0 + el;
        if (s < SS) {
            qh[oi] = __float2bfloat16(aq[r] * 0.125f);
            kh[oi] = __float2bfloat16(ak[r]);
            __nv_bfloat16 hb = __float2bfloat16(av[r]);
            vh[oi] = hb;
            vl[oi] = __float2bfloat16(av[r] - __bfloat162float(hb));
        } else {
            qh[oi] = __float2bfloat16(0.f);
            kh[oi] = __float2bfloat16(0.f);
            vh[oi] = __float2bfloat16(0.f);
            vl[oi] = __float2bfloat16(0.f);
        }
    }
}

// ---------------------------------------------------------------------------
// Attention v3: FA2-style mma.sync flash attention (unchanged from R12).
// ---------------------------------------------------------------------------
#define AT_ROW   144
#define AT_MAT   9216
#define AT_STAGE 27648
#define AT_SMEM  (AT_MAT + 2*AT_STAGE)

__global__ __launch_bounds__(128) void attn3_kernel(
        const __nv_bfloat16* __restrict__ Qh,
        const __nv_bfloat16* __restrict__ Kh,
        const __nv_bfloat16* __restrict__ Vh,
        const __nv_bfloat16* __restrict__ Vl,
        __nv_bfloat16* __restrict__ Oh,
        __nv_bfloat16* __restrict__ Ol)
{
    extern __shared__ char asmem[];
    const uint32_t sb   = smem_u32(asmem);
    const int bh   = blockIdx.x;
    const int qt   = blockIdx.y;
    const int tid  = threadIdx.x;
    const int lane = tid & 31;
    const int w    = tid >> 5;

    const size_t gbase = (size_t)bh * SP * HD;

    const int srow = tid >> 3;
    const int sc8  = (tid & 7) * 8;

#pragma unroll
    for (int it = 0; it < 4; it++) {
        int r = srow + it * 16;
        cp16(sb + r * AT_ROW + sc8 * 2,
             Qh + gbase + (size_t)(qt * 64 + r) * HD + sc8);
    }
    {
        const uint32_t base = sb + AT_MAT;
#pragma unroll
        for (int it = 0; it < 4; it++) {
            int r = srow + it * 16;
            size_t gi = gbase + (size_t)r * HD + sc8;
            uint32_t d = base + r * AT_ROW + sc8 * 2;
            cp16(d,              Kh + gi);
            cp16(d + AT_MAT,     Vh + gi);
            cp16(d + 2*AT_MAT,   Vl + gi);
        }
    }
    CP_COMMIT();

    const int l16   = lane & 15;
    const int arow  = l16;
    const int acsel = (lane >> 4) * 8;
    const int kbrow = l16 & 7;
    const int kbsel = (l16 >> 3) * 8;
    const int vrow  = l16;
    const int vcsel = (lane & 16) ? 8 : 0;

    uint32_t qf[4][4];
    float of[8][4] = {};
    float m_lo = -1e30f, m_hi = -1e30f, l_lo = 0.f, l_hi = 0.f;

    CP_WAIT0();
    __syncthreads();

#pragma unroll
    for (int kk = 0; kk < 4; kk++) {
        uint32_t a = sb + (w * 16 + arow) * AT_ROW + (kk * 16 + acsel) * 2;
        LDMATRIX_X4(qf[kk], a);
    }

    for (int kt = 0; kt < SP / 64; kt++) {
        if (kt > 0) { CP_WAIT0(); __syncthreads(); }
        if (kt + 1 < SP / 64) {
            const uint32_t base = sb + AT_MAT + ((kt + 1) & 1) * AT_STAGE;
            const size_t   gr   = gbase + (size_t)((kt + 1) * 64) * HD;
#pragma unroll
            for (int it = 0; it < 4; it++) {
                int r = srow + it * 16;
                size_t gi = gr + (size_t)r * HD + sc8;
                uint32_t d = base + r * AT_ROW + sc8 * 2;
                cp16(d,            Kh + gi);
                cp16(d + AT_MAT,   Vh + gi);
                cp16(d + 2*AT_MAT, Vl + gi);
            }
            CP_COMMIT();
        }
        const uint32_t kb = sb + AT_MAT + (kt & 1) * AT_STAGE;

        float sf[8][4];
#pragma unroll
        for (int nt = 0; nt < 8; nt++)
            sf[nt][0] = sf[nt][1] = sf[nt][2] = sf[nt][3] = 0.f;
#pragma unroll
        for (int kk = 0; kk < 4; kk++) {
#pragma unroll
            for (int nt = 0; nt < 8; nt++) {
                uint32_t bfr[2];
                LDMATRIX_X2(bfr, kb + (nt * 8 + kbrow) * AT_ROW + (kk * 16 + kbsel) * 2);
                MMA_BF16(sf[nt], qf[kk], bfr);
            }
        }
        if (kt == SP / 64 - 1) {
#pragma unroll
            for (int nt = 5; nt < 8; nt++)
                sf[nt][0] = sf[nt][1] = sf[nt][2] = sf[nt][3] = -1e30f;
        }

        float ml = -1e30f, mh = -1e30f;
#pragma unroll
        for (int nt = 0; nt < 8; nt++) {
            ml = fmaxf(ml, fmaxf(sf[nt][0], sf[nt][1]));
            mh = fmaxf(mh, fmaxf(sf[nt][2], sf[nt][3]));
        }
        ml = fmaxf(ml, __shfl_xor_sync(0xffffffffu, ml, 1));
        ml = fmaxf(ml, __shfl_xor_sync(0xffffffffu, ml, 2));
        mh = fmaxf(mh, __shfl_xor_sync(0xffffffffu, mh, 1));
        mh = fmaxf(mh, __shfl_xor_sync(0xffffffffu, mh, 2));

        float nml = fmaxf(m_lo, ml), nmh = fmaxf(m_hi, mh);
        float cl = __expf(m_lo - nml), ch = __expf(m_hi - nmh);
        m_lo = nml; m_hi = nmh;
        l_lo *= cl; l_hi *= ch;

#pragma unroll
        for (int nt = 0; nt < 8; nt++) {
            float p0 = __expf(sf[nt][0] - nml);
            float p1 = __expf(sf[nt][1] - nml);
            float p2 = __expf(sf[nt][2] - nmh);
            float p3 = __expf(sf[nt][3] - nmh);
            l_lo += p0 + p1;  l_hi += p2 + p3;
            sf[nt][0] = p0; sf[nt][1] = p1; sf[nt][2] = p2; sf[nt][3] = p3;
        }
#pragma unroll
        for (int dt = 0; dt < 8; dt++) {
            of[dt][0] *= cl; of[dt][1] *= cl;
            of[dt][2] *= ch; of[dt][3] *= ch;
        }

        const uint32_t vbh = kb + AT_MAT;
        const uint32_t vbl = kb + 2 * AT_MAT;
#pragma unroll
        for (int kc = 0; kc < 4; kc++) {
            const float* pA = sf[2 * kc];
            const float* pB = sf[2 * kc + 1];
            uint32_t ah[4], al[4];
            ah[0] = pk2(pA[0], pA[1]);
            ah[1] = pk2(pA[2], pA[3]);
            ah[2] = pk2(pB[0], pB[1]);
            ah[3] = pk2(pB[2], pB[3]);
            {
                float rA0 = pA[0] - __bfloat162float(__float2bfloat16(pA[0]));
                float rA1 = pA[1] - __bfloat162float(__float2bfloat16(pA[1]));
                float rA2 = pA[2] - __bfloat162float(__float2bfloat16(pA[2]));
                float rA3 = pA[3] - __bfloat162float(__float2bfloat16(pA[3]));
                float rB0 = pB[0] - __bfloat162float(__float2bfloat16(pB[0]));
                float rB1 = pB[1] - __bfloat162float(__float2bfloat16(pB[1]));
                float rB2 = pB[2] - __bfloat162float(__float2bfloat16(pB[2]));
                float rB3 = pB[3] - __bfloat162float(__float2bfloat16(pB[3]));
                al[0] = pk2(rA0, rA1);
                al[1] = pk2(rA2, rA3);
                al[2] = pk2(rB0, rB1);
                al[3] = pk2(rB2, rB3);
            }
#pragma unroll
            for (int dtp = 0; dtp < 4; dtp++) {
                uint32_t vh4[4], vl4[4];
                uint32_t vaddr = (kc * 16 + vrow) * AT_ROW + (dtp * 16 + vcsel) * 2;
                LDMATRIX_X4T(vh4, vbh + vaddr);
                LDMATRIX_X4T(vl4, vbl + vaddr);
                uint32_t bh0[2] = { vh4[0], vh4[1] };
                uint32_t bh1[2] = { vh4[2], vh4[3] };
                uint32_t bl0[2] = { vl4[0], vl4[1] };
                uint32_t bl1[2] = { vl4[2], vl4[3] };
                MMA_BF16(of[2 * dtp],     ah, bh0);
                MMA_BF16(of[2 * dtp + 1], ah, bh1);
                MMA_BF16(of[2 * dtp],     ah, bl0);
                MMA_BF16(of[2 * dtp + 1], ah, bl1);
                MMA_BF16(of[2 * dtp],     al, bh0);
                MMA_BF16(of[2 * dtp + 1], al, bh1);
            }
        }
    }

    l_lo += __shfl_xor_sync(0xffffffffu, l_lo, 1);
    l_lo += __shfl_xor_sync(0xffffffffu, l_lo, 2);
    l_hi += __shfl_xor_sync(0xffffffffu, l_hi, 1);
    l_hi += __shfl_xor_sync(0xffffffffu, l_hi, 2);
    float il = 1.f / l_lo, ih = 1.f / l_hi;

    const int b    = bh >> 3;
    const int hh2  = bh & 7;
    const int s_lo = qt * 64 + w * 16 + (lane >> 2);
    const int s_hi = s_lo + 8;
    const int dcol = hh2 * HD + 2 * (lane & 3);

#pragma unroll
    for (int dt = 0; dt < 8; dt++) {
        int d = dcol + dt * 8;
        if (s_lo < SS) {
            float v0 = of[dt][0] * il, v1 = of[dt][1] * il;
            float h0 = __bfloat162float(__float2bfloat16(v0));
            float h1 = __bfloat162float(__float2bfloat16(v1));
            size_t idx = (size_t)(b * SS + s_lo) * DD + d;
            *(uint32_t*)(Oh + idx) = pk2(v0, v1);
            *(uint32_t*)(Ol + idx) = pk2(v0 - h0, v1 - h1);
        }
        if (s_hi < SS) {
            float v2 = of[dt][2] * ih, v3 = of[dt][3] * ih;
            float h2 = __bfloat162float(__float2bfloat16(v2));
            float h3 = __bfloat162float(__float2bfloat16(v3));
            size_t idx = (size_t)(b * SS + s_hi) * DD + d;
            *(uint32_t*)(Oh + idx) = pk2(v2, v3);
            *(uint32_t*)(Ol + idx) = pk2(v2 - h2, v3 - h3);
        }
    }
}

// ---------------------------------------------------------------------------
// Tensor-core GEMM: product-reordered (reuse distance 4), x4 B-ldmatrix.
// RESID fp32 or split-bf16 (RSPLIT).
// ---------------------------------------------------------------------------
#define G_ROWB   80
#define G_MAT    10240
#define G_STAGE  40960
#define G_SMEM   81920

template<bool RELU, bool RESID, bool RSPLIT, bool PACKOUT>
__global__ __launch_bounds__(256, 2) void gemm_mma_kernel(
        const __nv_bfloat16* __restrict__ Ah, const __nv_bfloat16* __restrict__ Al,
        const __nv_bfloat16* __restrict__ Wh, const __nv_bfloat16* __restrict__ Wl,
        const float* __restrict__ bias,
        const float* __restrict__ R,
        const __nv_bfloat16* __restrict__ Rh, const __nv_bfloat16* __restrict__ Rl,
        float* __restrict__ Cf,
        __nv_bfloat16* __restrict__ Ch, __nv_bfloat16* __restrict__ Cl,
        int M, int N, int K)
{
    extern __shared__ char dsm[];
    const uint32_t sb = smem_u32(dsm);

    const int tid  = threadIdx.x;
    const int lane = tid & 31;
    const int wid  = tid >> 5;
    const int wm   = (wid & 1) * 64;
    const int wn   = (wid >> 1) * 32;
    const int m0   = blockIdx.y * 128;
    const int n0   = blockIdx.x * 128;

    float acc[4][4][4] = {};

    const int prow0 = tid >> 2;
    const int prow1 = prow0 + 64;
    const int pc8   = (tid & 3) * 8;
    const uint32_t pdst0 = (uint32_t)(prow0 * G_ROWB + pc8 * 2);
    const uint32_t pdst1 = (uint32_t)(prow1 * G_ROWB + pc8 * 2);

    const int arow  = lane & 15;
    const int acsel = (lane >> 4) * 8;

    const int nchunk = K >> 5;

    auto prefetch = [&](int kc, int st) {
        const int k0 = kc << 5;
        const uint32_t s0 = sb + st * G_STAGE;
        cp16(s0 + 0*G_MAT + pdst0, Ah + (size_t)(m0 + prow0) * K + k0 + pc8);
        cp16(s0 + 0*G_MAT + pdst1, Ah + (size_t)(m0 + prow1) * K + k0 + pc8);
        cp16(s0 + 1*G_MAT + pdst0, Al + (size_t)(m0 + prow0) * K + k0 + pc8);
        cp16(s0 + 1*G_MAT + pdst1, Al + (size_t)(m0 + prow1) * K + k0 + pc8);
        cp16(s0 + 2*G_MAT + pdst0, Wh + (size_t)(n0 + prow0) * K + k0 + pc8);
        cp16(s0 + 2*G_MAT + pdst1, Wh + (size_t)(n0 + prow1) * K + k0 + pc8);
        cp16(s0 + 3*G_MAT + pdst0, Wl + (size_t)(n0 + prow0) * K + k0 + pc8);
        cp16(s0 + 3*G_MAT + pdst1, Wl + (size_t)(n0 + prow1) * K + k0 + pc8);
    };

    prefetch(0, 0);
    CP_COMMIT();

    for (int kc = 0; kc < nchunk; kc++) {
        const int st = kc & 1;
        if (kc + 1 < nchunk) {
            prefetch(kc + 1, st ^ 1);
            CP_COMMIT();
            CP_WAIT1();
        } else {
            CP_WAIT0();
        }
        __syncthreads();

        const uint32_t s0 = sb + st * G_STAGE;
#pragma unroll
        for (int ks = 0; ks < 2; ks++) {
            const int kcol = ks * 16;

            // B fragments: one x4 per nt-pair (two frags each), hi and lo
            uint32_t bh[4][2], bl[4][2];
#pragma unroll
            for (int np = 0; np < 2; np++) {
                uint32_t r4b[4];
                uint32_t r = (uint32_t)((wn + np * 16 + arow) * G_ROWB + (kcol + acsel) * 2);
                LDMATRIX_X4(r4b, s0 + 2*G_MAT + r);
                bh[np*2    ][0] = r4b[0]; bh[np*2    ][1] = r4b[2];
                bh[np*2 + 1][0] = r4b[1]; bh[np*2 + 1][1] = r4b[3];
                LDMATRIX_X4(r4b, s0 + 3*G_MAT + r);
                bl[np*2    ][0] = r4b[0]; bl[np*2    ][1] = r4b[2];
                bl[np*2 + 1][0] = r4b[1]; bl[np*2 + 1][1] = r4b[3];
            }
#pragma unroll
            for (int mt = 0; mt < 4; mt++) {
                uint32_t ahf[4], alf[4];
                uint32_t r = (uint32_t)((wm + mt * 16 + arow) * G_ROWB + (kcol + acsel) * 2);
                LDMATRIX_X4(ahf, s0 + 0*G_MAT + r);
                LDMATRIX_X4(alf, s0 + 1*G_MAT + r);
                // product-major ordering: dependent MMAs 4 apart
#pragma unroll
                for (int nt = 0; nt < 4; nt++) MMA_BF16(acc[mt][nt], ahf, bh[nt]);
#pragma unroll
                for (int nt = 0; nt < 4; nt++) MMA_BF16(acc[mt][nt], ahf, bl[nt]);
#pragma unroll
                for (int nt = 0; nt < 4; nt++) MMA_BF16(acc[mt][nt], alf, bh[nt]);
            }
        }
        __syncthreads();
    }

    const int r4 = lane >> 2;
    const int c2 = (lane & 3) * 2;
#pragma unroll
    for (int mt = 0; mt < 4; mt++) {
#pragma unroll
        for (int nt = 0; nt < 4; nt++) {
#pragma unroll
            for (int e = 0; e < 4; e++) {
                int mg = m0 + wm + mt * 16 + r4 + (e >> 1) * 8;
                int ng = n0 + wn + nt * 8 + c2 + (e & 1);
                float v = acc[mt][nt][e] + bias[ng];
                if (RELU)  v = fmaxf(v, 0.f);
                if (RESID) {
                    if (RSPLIT)
                        v += __bfloat162float(Rh[(size_t)mg * N + ng])
                           + __bfloat162float(Rl[(size_t)mg * N + ng]);
                    else
                        v += R[(size_t)mg * N + ng];
                }
                if (PACKOUT) {
                    __nv_bfloat16 hb = __float2bfloat16(v);
                    Ch[(size_t)mg * N + ng] = hb;
                    Cl[(size_t)mg * N + ng] = __float2bfloat16(v - __bfloat162float(hb));
                } else {
                    Cf[(size_t)mg * N + ng] = v;
                }
            }
        }
    }
}

// ---------------------------------------------------------------------------
// LayerNorm; PACK=1 writes only the split-bf16 pair, PACK=0 only fp32.
// ---------------------------------------------------------------------------
template<bool PACK>
__global__ void ln_kernel(const float* __restrict__ x,
                          const float* __restrict__ w,
                          const float* __restrict__ b,
                          float* __restrict__ y,
                          __nv_bfloat16* __restrict__ yh,
                          __nv_bfloat16* __restrict__ yl)
{
    int r = blockIdx.x;
    int t = threadIdx.x;
    const float* xr = x + (size_t)r * DD;

    float v0 = xr[t], v1 = xr[t + 256];
    float s  = v0 + v1;
    float sq = v0 * v0 + v1 * v1;

#pragma unroll
    for (int off = 16; off; off >>= 1) {
        s  += __shfl_xor_sync(0xffffffffu, s,  off);
        sq += __shfl_xor_sync(0xffffffffu, sq, off);
    }
    __shared__ float sw[8], sqw[8];
    if ((t & 31) == 0) { sw[t >> 5] = s; sqw[t >> 5] = sq; }
    __syncthreads();
    s  = sw[0] + sw[1] + sw[2] + sw[3] + sw[4] + sw[5] + sw[6] + sw[7];
    sq = sqw[0] + sqw[1] + sqw[2] + sqw[3] + sqw[4] + sqw[5] + sqw[6] + sqw[7];

    float mean = s * (1.f / DD);
    float var  = sq * (1.f / DD) - mean * mean;
    float inv  = rsqrtf(var + 1e-5f);

    float r0 = (v0 - mean) * inv * w[t]       + b[t];
    float r1 = (v1 - mean) * inv * w[t + 256] + b[t + 256];
    if (!PACK) {
        float* yr = y + (size_t)r * DD;
        yr[t]       = r0;
        yr[t + 256] = r1;
    } else {
        size_t base = (size_t)r * DD;
        __nv_bfloat16 h0 = __float2bfloat16(r0);
        __nv_bfloat16 h1 = __float2bfloat16(r1);
        yh[base + t]       = h0;
        yh[base + t + 256] = h1;
        yl[base + t]       = __float2bfloat16(r0 - __bfloat162float(h0));
        yl[base + t + 256] = __float2bfloat16(r1 - __bfloat162float(h1));
    }
}

// ---------------------------------------------------------------------------
// Host launcher
// ---------------------------------------------------------------------------
extern "C" void kernel_launch(void* const* d_in, const int* in_sizes, int n_in,
                              void* d_out, int out_size)
{
    const int*   x    = (const int*)  d_in[0];
    const float* emb  = (const float*)d_in[1];
    const float* pe   = (const float*)d_in[2];
    const float* Wq   = (const float*)d_in[3];
    const float* Wk   = (const float*)d_in[4];
    const float* Wv   = (const float*)d_in[5];
    const float* Wo   = (const float*)d_in[6];
    const float* bo   = (const float*)d_in[7];
    const float* ln1w = (const float*)d_in[8];
    const float* ln1b = (const float*)d_in[9];
    const float* W1   = (const float*)d_in[10];
    const float* b1   = (const float*)d_in[11];
    const float* W2   = (const float*)d_in[12];
    const float* b2   = (const float*)d_in[13];
    const float* ln2w = (const float*)d_in[14];
    const float* ln2b = (const float*)d_in[15];
    float* out = (float*)d_out;

    float *h, *t;
    __nv_bfloat16 *qh, *kh, *vh, *vl;
    __nv_bfloat16 *oh, *ol, *n1h, *n1l, *ffh, *ffl;
    __nv_bfloat16 *woh, *wol, *w1h, *w1l, *w2h, *w2l;
    cudaGetSymbolAddress((void**)&h,   g_h);
    cudaGetSymbolAddress((void**)&t,   g_t);
    cudaGetSymbolAddress((void**)&qh,  g_qh);
    cudaGetSymbolAddress((void**)&kh,  g_kh);
    cudaGetSymbolAddress((void**)&vh,  g_vh);
    cudaGetSymbolAddress((void**)&vl,  g_vl);
    cudaGetSymbolAddress((void**)&oh,  g_oh);
    cudaGetSymbolAddress((void**)&ol,  g_ol);
    cudaGetSymbolAddress((void**)&n1h, g_n1h);
    cudaGetSymbolAddress((void**)&n1l, g_n1l);
    cudaGetSymbolAddress((void**)&ffh, g_ffh);
    cudaGetSymbolAddress((void**)&ffl, g_ffl);
    cudaGetSymbolAddress((void**)&woh, g_woh);
    cudaGetSymbolAddress((void**)&wol, g_wol);
    cudaGetSymbolAddress((void**)&w1h, g_w1h);
    cudaGetSymbolAddress((void**)&w1l, g_w1l);
    cudaGetSymbolAddress((void**)&w2h, g_w2h);
    cudaGetSymbolAddress((void**)&w2l, g_w2l);

    cudaFuncSetAttribute(gemm_mma_kernel<false, true,  false, false>,
                         cudaFuncAttributeMaxDynamicSharedMemorySize, G_SMEM);
    cudaFuncSetAttribute(gemm_mma_kernel<false, true,  true,  false>,
                         cudaFuncAttributeMaxDynamicSharedMemorySize, G_SMEM);
    cudaFuncSetAttribute(gemm_mma_kernel<true,  false, false, true>,
                         cudaFuncAttributeMaxDynamicSharedMemorySize, G_SMEM);
    cudaFuncSetAttribute(attn3_kernel,
                         cudaFuncAttributeMaxDynamicSharedMemorySize, AT_SMEM);

    // Launch order: attn3 (layer 0) sits at stream index 3 for ncu.
    pack2_kernel<<<(LL*DD*DD + 255) / 256, 256>>>(Wo, woh, wol, LL*DD*DD);    // 0
    embed_kernel<<<MM * DD / 256, 256>>>(x, emb, pe, h);                      // 1

    for (int l = 0; l < LL; l++) {
        qkv2_kernel<<<dim3(BB * HH, SP / 32, 2), 256>>>(                      // 2 (l=0)
            h, Wq + l * HD * HD, Wk + l * HD * HD, Wv + l * HD * HD,
            qh, kh, vh, vl);

        attn3_kernel<<<dim3(BB * HH, SP / 64), 128, AT_SMEM>>>(               // 3 (l=0)
            qh, kh, vh, vl, oh, ol);

        if (l == 0) {
            pack2_kernel<<<(LL*FF*DD + 255) / 256, 256>>>(W1, w1h, w1l, LL*FF*DD);
            pack2_kernel<<<(LL*DD*FF + 255) / 256, 256>>>(W2, w2h, w2l, LL*DD*FF);
        }

        // t = o @ Wo^T + bo + h   (fp32 residual, fp32 out)
        gemm_mma_kernel<false, true, false, false><<<dim3(DD / 128, MM / 128), 256, G_SMEM>>>(
            oh, ol, woh + (size_t)l * DD * DD, wol + (size_t)l * DD * DD,
            bo + l * DD, h, nullptr, nullptr, t, nullptr, nullptr, MM, DD, DD);

        ln_kernel<true><<<MM, 256>>>(t, ln1w + l * DD, ln1b + l * DD,
                                     nullptr, n1h, n1l);

        // ff = relu(n1 @ W1^T + b1)  (split-bf16 out)
        gemm_mma_kernel<true, false, false, true><<<dim3(FF / 128, MM / 128), 256, G_SMEM>>>(
            n1h, n1l, w1h + (size_t)l * FF * DD, w1l + (size_t)l * FF * DD,
            b1 + l * FF, nullptr, nullptr, nullptr, nullptr, ffh, ffl, MM, FF, DD);

        // t = ff @ W2^T + b2 + n1  (split residual, fp32 out)
        gemm_mma_kernel<false, true, true, false><<<dim3(DD / 128, MM / 128), 256, G_SMEM>>>(
            ffh, ffl, w2h + (size_t)l * DD * FF, w2l + (size_t)l * DD * FF,
            b2 + l * DD, nullptr, n1h, n1l, t, nullptr, nullptr, MM, DD, FF);

        float* dst = (l == LL - 1) ? out : h;
        ln_kernel<false><<<MM, 256>>>(t, ln2w + l * DD, ln2b + l * DD,
                                      dst, nullptr, nullptr);
    }
}